// round 1
// baseline (speedup 1.0000x reference)
#include <cuda_runtime.h>
#include <math.h>

#define B_   2
#define T_   2048
#define BT_  (B_*T_)
#define DM_  1024
#define H_   16
#define DH_  64
#define DC1_ 384
#define DC_  256
#define DR_  32
#define DQK_ 96

// ---------------- scratch (device globals: alloc-free) ----------------
__device__ float g_cq    [BT_*DC1_];
__device__ float g_ckv   [BT_*DC_];
__device__ float g_krot  [BT_*DR_];
__device__ float g_qstate[BT_*DM_];
__device__ float g_qrot  [BT_*H_*DR_];
__device__ float g_kstate[BT_*DM_];
__device__ float g_vstate[BT_*DM_];
__device__ float g_qf    [BT_*H_*DQK_];
__device__ float g_kf    [BT_*H_*DQK_];
__device__ float g_attn  [BT_*DM_];

// ---------------- generic tiled fp32 GEMM: C[M,N] = A[M,K] @ B[K,N] ----------------
// BM=BN=64, BK=16, 256 threads, 4x4 per-thread tile. M%64==0, K%16==0, N%4==0 assumed.
__global__ void gemm64(const float* __restrict__ A, const float* __restrict__ Bm,
                       float* __restrict__ C, int M, int N, int K) {
    __shared__ float As[16][64];    // transposed A tile
    __shared__ float Bs[16][68];    // padded B tile
    const int tid = threadIdx.x;
    const int ty  = tid >> 4, tx = tid & 15;
    const int m0  = blockIdx.y << 6;
    const int n0  = blockIdx.x << 6;
    const int la_m = tid >> 2;
    const int la_k = (tid & 3) << 2;
    const int lb_k = tid >> 4;
    const int lb_n = (tid & 15) << 2;

    float acc[4][4] = {};
    for (int k0 = 0; k0 < K; k0 += 16) {
        float4 av = *(const float4*)(A + (size_t)(m0 + la_m) * K + k0 + la_k);
        As[la_k + 0][la_m] = av.x;
        As[la_k + 1][la_m] = av.y;
        As[la_k + 2][la_m] = av.z;
        As[la_k + 3][la_m] = av.w;
        if (n0 + lb_n < N) {
            *(float4*)&Bs[lb_k][lb_n] =
                *(const float4*)(Bm + (size_t)(k0 + lb_k) * N + n0 + lb_n);
        } else {
            *(float4*)&Bs[lb_k][lb_n] = make_float4(0.f, 0.f, 0.f, 0.f);
        }
        __syncthreads();
        #pragma unroll
        for (int k = 0; k < 16; k++) {
            float a[4], b[4];
            *(float4*)a = *(const float4*)&As[k][ty << 2];
            *(float4*)b = *(const float4*)&Bs[k][tx << 2];
            #pragma unroll
            for (int i = 0; i < 4; i++)
                #pragma unroll
                for (int j = 0; j < 4; j++)
                    acc[i][j] += a[i] * b[j];
        }
        __syncthreads();
    }
    #pragma unroll
    for (int i = 0; i < 4; i++) {
        int m = m0 + (ty << 2) + i;
        #pragma unroll
        for (int j = 0; j < 4; j++) {
            int n = n0 + (tx << 2) + j;
            if (n < N) C[(size_t)m * N + n] = acc[i][j];
        }
    }
}

// ---------------- RoPE + concat + RMS-norm: build q_final / k_final ----------------
// one block (96 threads) per (bt, h); handles both q and k
__global__ void build_qk_kernel() {
    const int blk = blockIdx.x;           // bt*H + h
    const int bt  = blk >> 4;
    const int h   = blk & 15;
    const int t   = bt & (T_ - 1);
    const int d   = threadIdx.x;          // 0..95

    float qv, kv;
    if (d < DH_) {
        qv = g_qstate[(size_t)bt * DM_ + h * DH_ + d];
        kv = g_kstate[(size_t)bt * DM_ + h * DH_ + d];
    } else {
        const int dr = d - DH_;           // 0..31
        const int j  = dr & 15;           // freq index
        float inv = powf(10000.f, -(float)j * (1.f / 16.f));
        float ang = (float)t * inv;
        float c = cosf(ang), sn = sinf(ang);
        const float* qr = g_qrot + (size_t)bt * (H_ * DR_) + h * DR_;
        const float* kr = g_krot + (size_t)bt * DR_;
        float x1 = qr[j], x2 = qr[16 + j];
        float y1 = kr[j], y2 = kr[16 + j];
        if (dr < 16) { qv = x1 * c - x2 * sn;  kv = y1 * c - y2 * sn; }
        else         { qv = x1 * sn + x2 * c;  kv = y1 * sn + y2 * c; }
    }
    float q2 = qv * qv, k2 = kv * kv;
    #pragma unroll
    for (int o = 16; o > 0; o >>= 1) {
        q2 += __shfl_xor_sync(0xffffffffu, q2, o);
        k2 += __shfl_xor_sync(0xffffffffu, k2, o);
    }
    __shared__ float pq[3], pk[3];
    const int w = d >> 5;
    if ((d & 31) == 0) { pq[w] = q2; pk[w] = k2; }
    __syncthreads();
    float sq = pq[0] + pq[1] + pq[2];
    float sk = pk[0] + pk[1] + pk[2];
    float rq = rsqrtf(sq * (1.f / 96.f) + 1e-6f);
    float rk = rsqrtf(sk * (1.f / 96.f) + 1e-6f);
    g_qf[(size_t)blk * DQK_ + d] = qv * rq;
    g_kf[(size_t)blk * DQK_ + d] = kv * rk;
}

// ---------------- causal flash attention, fp32, 64x64 tiles ----------------
// smem floats: Qs 64*100 | Kt 96*68 (K transposed) | Vs 64*68 | Ps 64*68
#define FLASH_SMEM ((64*100 + 96*68 + 64*68 + 64*68) * 4)

__global__ void flash_kernel() {
    extern __shared__ float sm[];
    float* Qs = sm;                 // [64][100]
    float* Kt = Qs + 64 * 100;      // [96][68]  (d-major)
    float* Vs = Kt + 96 * 68;       // [64][68]
    float* Ps = Vs + 64 * 68;       // [64][68]

    const int qt = blockIdx.x;      // 0..31 query tile
    const int h  = blockIdx.y;
    const int b  = blockIdx.z;
    const int tid = threadIdx.x;
    const int ty = tid >> 4, tx = tid & 15;
    const float scale = 0.10206207261596577f;   // 1/sqrt(96)

    const float* qbase = g_qf + (((size_t)b * T_ + qt * 64) * H_ + h) * DQK_;
    for (int i = tid; i < 64 * 24; i += 256) {
        int r = i / 24, c4 = i % 24;
        float4 v = *(const float4*)(qbase + (size_t)r * (H_ * DQK_) + (c4 << 2));
        v.x *= scale; v.y *= scale; v.z *= scale; v.w *= scale;
        *(float4*)&Qs[r * 100 + (c4 << 2)] = v;
    }

    float m_i[4], l_i[4], O[4][4];
    #pragma unroll
    for (int i = 0; i < 4; i++) {
        m_i[i] = -1e30f; l_i[i] = 0.f;
        #pragma unroll
        for (int j = 0; j < 4; j++) O[i][j] = 0.f;
    }

    for (int kt = 0; kt <= qt; kt++) {
        const float* kbase = g_kf     + (((size_t)b * T_ + kt * 64) * H_ + h) * DQK_;
        const float* vbase = g_vstate + ((size_t)b * T_ + kt * 64) * DM_ + h * DH_;

        __syncthreads();  // previous PV reads done before overwriting Kt/Vs (also covers Qs on iter 0)
        for (int i = tid; i < 64 * 24; i += 256) {
            int r = i / 24, c4 = i % 24;
            float4 v = *(const float4*)(kbase + (size_t)r * (H_ * DQK_) + (c4 << 2));
            int d0 = c4 << 2;
            Kt[(d0 + 0) * 68 + r] = v.x;
            Kt[(d0 + 1) * 68 + r] = v.y;
            Kt[(d0 + 2) * 68 + r] = v.z;
            Kt[(d0 + 3) * 68 + r] = v.w;
        }
        for (int i = tid; i < 64 * 16; i += 256) {
            int r = i / 16, c4 = i % 16;
            *(float4*)&Vs[r * 68 + (c4 << 2)] =
                *(const float4*)(vbase + (size_t)r * DM_ + (c4 << 2));
        }
        __syncthreads();

        // S = Q @ K^T  (per-thread 4x4)
        float s[4][4] = {};
        #pragma unroll 4
        for (int d = 0; d < 96; d++) {
            float4 kv = *(const float4*)&Kt[d * 68 + (tx << 2)];
            #pragma unroll
            for (int i = 0; i < 4; i++) {
                float q = Qs[(ty * 4 + i) * 100 + d];
                s[i][0] += q * kv.x; s[i][1] += q * kv.y;
                s[i][2] += q * kv.z; s[i][3] += q * kv.w;
            }
        }
        if (kt == qt) {
            #pragma unroll
            for (int i = 0; i < 4; i++)
                #pragma unroll
                for (int j = 0; j < 4; j++)
                    if (tx * 4 + j > ty * 4 + i) s[i][j] = -1e30f;
        }

        // online softmax (rows live in 16-lane tx groups)
        #pragma unroll
        for (int i = 0; i < 4; i++) {
            float mx = fmaxf(fmaxf(s[i][0], s[i][1]), fmaxf(s[i][2], s[i][3]));
            #pragma unroll
            for (int o = 1; o < 16; o <<= 1) mx = fmaxf(mx, __shfl_xor_sync(0xffffffffu, mx, o));
            float mnew = fmaxf(m_i[i], mx);
            float corr = __expf(m_i[i] - mnew);
            m_i[i] = mnew;
            float rs = 0.f;
            #pragma unroll
            for (int j = 0; j < 4; j++) { float p = __expf(s[i][j] - mnew); s[i][j] = p; rs += p; }
            #pragma unroll
            for (int o = 1; o < 16; o <<= 1) rs += __shfl_xor_sync(0xffffffffu, rs, o);
            l_i[i] = l_i[i] * corr + rs;
            #pragma unroll
            for (int j = 0; j < 4; j++) O[i][j] *= corr;
            *(float4*)&Ps[(ty * 4 + i) * 68 + (tx << 2)] = *(float4*)s[i];
        }
        __syncthreads();

        // O += P @ V
        #pragma unroll 4
        for (int j = 0; j < 64; j++) {
            float4 vv = *(const float4*)&Vs[j * 68 + (tx << 2)];
            #pragma unroll
            for (int i = 0; i < 4; i++) {
                float p = Ps[(ty * 4 + i) * 68 + j];
                O[i][0] += p * vv.x; O[i][1] += p * vv.y;
                O[i][2] += p * vv.z; O[i][3] += p * vv.w;
            }
        }
    }

    float* obase = g_attn + ((size_t)b * T_ + qt * 64) * DM_ + h * DH_;
    #pragma unroll
    for (int i = 0; i < 4; i++) {
        float inv = 1.f / l_i[i];
        #pragma unroll
        for (int j = 0; j < 4; j++)
            obase[(size_t)(ty * 4 + i) * DM_ + (tx << 2) + j] = O[i][j] * inv;
    }
}

// ---------------- launch ----------------
extern "C" void kernel_launch(void* const* d_in, const int* in_sizes, int n_in,
                              void* d_out, int out_size) {
    const float* x     = (const float*)d_in[0];
    const float* w_dq  = (const float*)d_in[1];
    const float* w_uq  = (const float*)d_in[2];
    const float* w_rq  = (const float*)d_in[3];
    const float* w_dkv = (const float*)d_in[4];
    const float* w_rk  = (const float*)d_in[5];
    const float* w_uk  = (const float*)d_in[6];
    const float* w_uv  = (const float*)d_in[7];
    const float* w_o   = (const float*)d_in[8];
    float* out = (float*)d_out;

    float *cq, *ckv, *krot, *qstate, *qrot, *kstate, *vstate, *attn;
    cudaGetSymbolAddress((void**)&cq,     g_cq);
    cudaGetSymbolAddress((void**)&ckv,    g_ckv);
    cudaGetSymbolAddress((void**)&krot,   g_krot);
    cudaGetSymbolAddress((void**)&qstate, g_qstate);
    cudaGetSymbolAddress((void**)&qrot,   g_qrot);
    cudaGetSymbolAddress((void**)&kstate, g_kstate);
    cudaGetSymbolAddress((void**)&vstate, g_vstate);
    cudaGetSymbolAddress((void**)&attn,   g_attn);

    #define GRID(N) dim3(((N) + 63) / 64, BT_ / 64)
    gemm64<<<GRID(DC1_),     256>>>(x,   w_dq,  cq,     BT_, DC1_,     DM_);
    gemm64<<<GRID(DC_),      256>>>(x,   w_dkv, ckv,    BT_, DC_,      DM_);
    gemm64<<<GRID(DR_),      256>>>(x,   w_rk,  krot,   BT_, DR_,      DM_);
    gemm64<<<GRID(DM_),      256>>>(cq,  w_uq,  qstate, BT_, DM_,      DC1_);
    gemm64<<<GRID(H_ * DR_), 256>>>(cq,  w_rq,  qrot,   BT_, H_ * DR_, DC1_);
    gemm64<<<GRID(DM_),      256>>>(ckv, w_uk,  kstate, BT_, DM_,      DC_);
    gemm64<<<GRID(DM_),      256>>>(ckv, w_uv,  vstate, BT_, DM_,      DC_);

    build_qk_kernel<<<BT_ * H_, 96>>>();

    cudaFuncSetAttribute(flash_kernel, cudaFuncAttributeMaxDynamicSharedMemorySize, FLASH_SMEM);
    flash_kernel<<<dim3(T_ / 64, H_, B_), 256, FLASH_SMEM>>>();

    gemm64<<<GRID(DM_), 256>>>(attn, w_o, out, BT_, DM_, DM_);
    #undef GRID
}

// round 3
// speedup vs baseline: 1.4063x; 1.4063x over previous
#include <cuda_runtime.h>
#include <stdint.h>
#include <math.h>

#define B_   2
#define T_   2048
#define BT_  (B_*T_)
#define DM_  1024
#define H_   16
#define DH_  64
#define DC1_ 384
#define DC_  256
#define DR_  32
#define DQK_ 96

// ---------------- scratch (device globals: alloc-free) ----------------
__device__ float g_cq    [BT_*DC1_];
__device__ float g_ckv   [BT_*DC_];
__device__ float g_krot  [BT_*DR_];
__device__ float g_qstate[BT_*DM_];
__device__ float g_qrot  [BT_*H_*DR_];
__device__ float g_kstate[BT_*DM_];
__device__ float g_vstate[BT_*DM_];
__device__ float g_qf    [BT_*H_*DQK_];
__device__ float g_kf    [BT_*H_*DQK_];
__device__ float g_attn  [BT_*DM_];

// ---------------- TF32 tensor-core GEMM: C[M,N] = A[M,K] @ B[K,N] ----------------
// 128x128x16 block tile, 8 warps (2x4), warp tile 64x32, mma m16n8k8 tf32.
// Double-buffered cp.async pipeline. M%128==0, K%16==0, N%4==0.

__device__ __forceinline__ unsigned f2tf(float f) {
    unsigned u; asm("cvt.rna.tf32.f32 %0, %1;" : "=r"(u) : "f"(f)); return u;
}

__device__ __forceinline__ void mma_tf32(float* c, const unsigned* a, const unsigned* b) {
    asm volatile(
        "mma.sync.aligned.m16n8k8.row.col.f32.tf32.tf32.f32 "
        "{%0,%1,%2,%3}, {%4,%5,%6,%7}, {%8,%9}, {%0,%1,%2,%3};"
        : "+f"(c[0]), "+f"(c[1]), "+f"(c[2]), "+f"(c[3])
        : "r"(a[0]), "r"(a[1]), "r"(a[2]), "r"(a[3]), "r"(b[0]), "r"(b[1]));
}

__global__ __launch_bounds__(256) void gemm_tf32(
        const float* __restrict__ A, const float* __restrict__ Bm,
        float* __restrict__ C, int M, int N, int K) {
    __shared__ float As[2][128][20];   // [m][k], row stride 20
    __shared__ float Bs[2][16][136];   // [k][n], row stride 136 (mod 32 == 8)

    const int tid  = threadIdx.x;
    const int lane = tid & 31, warp = tid >> 5;
    const int gr = lane >> 2, tg = lane & 3;
    const int m0 = blockIdx.y << 7;
    const int n0 = blockIdx.x << 7;
    const int wm = (warp >> 2) << 6;   // 0 / 64
    const int wn = (warp & 3) << 5;    // 0 / 32 / 64 / 96

    float acc[4][4][4];
    #pragma unroll
    for (int i = 0; i < 4; i++)
        #pragma unroll
        for (int j = 0; j < 4; j++)
            #pragma unroll
            for (int r = 0; r < 4; r++) acc[i][j][r] = 0.f;

    #define LOAD_STAGE(BUF, K0)                                                       \
    {                                                                                 \
        _Pragma("unroll")                                                             \
        for (int u = 0; u < 2; u++) {                                                 \
            int idx = tid + (u << 8);                                                 \
            int r = idx >> 2, kq = (idx & 3) << 2;                                    \
            unsigned d = (unsigned)__cvta_generic_to_shared(&As[BUF][r][kq]);         \
            const float* s = A + (size_t)(m0 + r) * K + (K0) + kq;                    \
            asm volatile("cp.async.ca.shared.global [%0], [%1], 16;\n"                \
                         :: "r"(d), "l"(s));                                          \
        }                                                                             \
        _Pragma("unroll")                                                             \
        for (int u = 0; u < 2; u++) {                                                 \
            int idx = tid + (u << 8);                                                 \
            int r = idx >> 5, nq = (idx & 31) << 2;                                   \
            unsigned d = (unsigned)__cvta_generic_to_shared(&Bs[BUF][r][nq]);         \
            const float* s = Bm + (size_t)((K0) + r) * N + n0 + nq;                   \
            int sz = (n0 + nq < N) ? 16 : 0;                                          \
            asm volatile("cp.async.ca.shared.global [%0], [%1], 16, %2;\n"            \
                         :: "r"(d), "l"(s), "r"(sz));                                 \
        }                                                                             \
        asm volatile("cp.async.commit_group;\n");                                     \
    }

    int buf = 0;
    LOAD_STAGE(0, 0);

    for (int k0 = 0; k0 < K; k0 += 16) {
        if (k0 + 16 < K) {
            LOAD_STAGE(buf ^ 1, k0 + 16);
            asm volatile("cp.async.wait_group 1;\n");
        } else {
            asm volatile("cp.async.wait_group 0;\n");
        }
        __syncthreads();

        #pragma unroll
        for (int kk = 0; kk < 16; kk += 8) {
            unsigned af[4][4], bf[4][2];
            #pragma unroll
            for (int mt = 0; mt < 4; mt++) {
                int m = wm + (mt << 4);
                af[mt][0] = f2tf(As[buf][m + gr    ][kk + tg    ]);
                af[mt][1] = f2tf(As[buf][m + gr + 8][kk + tg    ]);
                af[mt][2] = f2tf(As[buf][m + gr    ][kk + tg + 4]);
                af[mt][3] = f2tf(As[buf][m + gr + 8][kk + tg + 4]);
            }
            #pragma unroll
            for (int nt = 0; nt < 4; nt++) {
                int n = wn + (nt << 3);
                bf[nt][0] = f2tf(Bs[buf][kk + tg    ][n + gr]);
                bf[nt][1] = f2tf(Bs[buf][kk + tg + 4][n + gr]);
            }
            #pragma unroll
            for (int mt = 0; mt < 4; mt++)
                #pragma unroll
                for (int nt = 0; nt < 4; nt++)
                    mma_tf32(acc[mt][nt], af[mt], bf[nt]);
        }
        __syncthreads();
        buf ^= 1;
    }
    #undef LOAD_STAGE

    #pragma unroll
    for (int mt = 0; mt < 4; mt++) {
        #pragma unroll
        for (int nt = 0; nt < 4; nt++) {
            int m = m0 + wm + (mt << 4) + gr;
            int n = n0 + wn + (nt << 3) + (tg << 1);
            if (n < N) {
                *(float2*)&C[(size_t)m * N + n]       = make_float2(acc[mt][nt][0], acc[mt][nt][1]);
                *(float2*)&C[(size_t)(m + 8) * N + n] = make_float2(acc[mt][nt][2], acc[mt][nt][3]);
            }
        }
    }
}

// ---------------- RoPE + concat + RMS-norm: build q_final / k_final ----------------
__global__ void build_qk_kernel() {
    const int blk = blockIdx.x;           // bt*H + h
    const int bt  = blk >> 4;
    const int h   = blk & 15;
    const int t   = bt & (T_ - 1);
    const int d   = threadIdx.x;          // 0..95

    float qv, kv;
    if (d < DH_) {
        qv = g_qstate[(size_t)bt * DM_ + h * DH_ + d];
        kv = g_kstate[(size_t)bt * DM_ + h * DH_ + d];
    } else {
        const int dr = d - DH_;           // 0..31
        const int j  = dr & 15;           // freq index
        float inv = powf(10000.f, -(float)j * (1.f / 16.f));
        float ang = (float)t * inv;
        float c = cosf(ang), sn = sinf(ang);
        const float* qr = g_qrot + (size_t)bt * (H_ * DR_) + h * DR_;
        const float* kr = g_krot + (size_t)bt * DR_;
        float x1 = qr[j], x2 = qr[16 + j];
        float y1 = kr[j], y2 = kr[16 + j];
        if (dr < 16) { qv = x1 * c - x2 * sn;  kv = y1 * c - y2 * sn; }
        else         { qv = x1 * sn + x2 * c;  kv = y1 * sn + y2 * c; }
    }
    float q2 = qv * qv, k2 = kv * kv;
    #pragma unroll
    for (int o = 16; o > 0; o >>= 1) {
        q2 += __shfl_xor_sync(0xffffffffu, q2, o);
        k2 += __shfl_xor_sync(0xffffffffu, k2, o);
    }
    __shared__ float pq[3], pk[3];
    const int w = d >> 5;
    if ((d & 31) == 0) { pq[w] = q2; pk[w] = k2; }
    __syncthreads();
    float sq = pq[0] + pq[1] + pq[2];
    float sk = pk[0] + pk[1] + pk[2];
    float rq = rsqrtf(sq * (1.f / 96.f) + 1e-6f);
    float rk = rsqrtf(sk * (1.f / 96.f) + 1e-6f);
    g_qf[(size_t)blk * DQK_ + d] = qv * rq;
    g_kf[(size_t)blk * DQK_ + d] = kv * rk;
}

// ---------------- causal flash attention, fp32, 64x64 tiles ----------------
#define FLASH_SMEM ((64*100 + 96*68 + 64*68 + 64*68) * 4)

__global__ void flash_kernel() {
    extern __shared__ float sm[];
    float* Qs = sm;                 // [64][100]
    float* Kt = Qs + 64 * 100;      // [96][68]  (d-major)
    float* Vs = Kt + 96 * 68;       // [64][68]
    float* Ps = Vs + 64 * 68;       // [64][68]

    const int qt = blockIdx.x;      // 0..31 query tile
    const int h  = blockIdx.y;
    const int b  = blockIdx.z;
    const int tid = threadIdx.x;
    const int ty = tid >> 4, tx = tid & 15;
    const float scale = 0.10206207261596577f;   // 1/sqrt(96)

    const float* qbase = g_qf + (((size_t)b * T_ + qt * 64) * H_ + h) * DQK_;
    for (int i = tid; i < 64 * 24; i += 256) {
        int r = i / 24, c4 = i % 24;
        float4 v = *(const float4*)(qbase + (size_t)r * (H_ * DQK_) + (c4 << 2));
        v.x *= scale; v.y *= scale; v.z *= scale; v.w *= scale;
        *(float4*)&Qs[r * 100 + (c4 << 2)] = v;
    }

    float m_i[4], l_i[4], O[4][4];
    #pragma unroll
    for (int i = 0; i < 4; i++) {
        m_i[i] = -1e30f; l_i[i] = 0.f;
        #pragma unroll
        for (int j = 0; j < 4; j++) O[i][j] = 0.f;
    }

    for (int kt = 0; kt <= qt; kt++) {
        const float* kbase = g_kf     + (((size_t)b * T_ + kt * 64) * H_ + h) * DQK_;
        const float* vbase = g_vstate + ((size_t)b * T_ + kt * 64) * DM_ + h * DH_;

        __syncthreads();
        for (int i = tid; i < 64 * 24; i += 256) {
            int r = i / 24, c4 = i % 24;
            float4 v = *(const float4*)(kbase + (size_t)r * (H_ * DQK_) + (c4 << 2));
            int d0 = c4 << 2;
            Kt[(d0 + 0) * 68 + r] = v.x;
            Kt[(d0 + 1) * 68 + r] = v.y;
            Kt[(d0 + 2) * 68 + r] = v.z;
            Kt[(d0 + 3) * 68 + r] = v.w;
        }
        for (int i = tid; i < 64 * 16; i += 256) {
            int r = i / 16, c4 = i % 16;
            *(float4*)&Vs[r * 68 + (c4 << 2)] =
                *(const float4*)(vbase + (size_t)r * DM_ + (c4 << 2));
        }
        __syncthreads();

        float s[4][4] = {};
        #pragma unroll 4
        for (int d = 0; d < 96; d++) {
            float4 kv = *(const float4*)&Kt[d * 68 + (tx << 2)];
            #pragma unroll
            for (int i = 0; i < 4; i++) {
                float q = Qs[(ty * 4 + i) * 100 + d];
                s[i][0] += q * kv.x; s[i][1] += q * kv.y;
                s[i][2] += q * kv.z; s[i][3] += q * kv.w;
            }
        }
        if (kt == qt) {
            #pragma unroll
            for (int i = 0; i < 4; i++)
                #pragma unroll
                for (int j = 0; j < 4; j++)
                    if (tx * 4 + j > ty * 4 + i) s[i][j] = -1e30f;
        }

        #pragma unroll
        for (int i = 0; i < 4; i++) {
            float mx = fmaxf(fmaxf(s[i][0], s[i][1]), fmaxf(s[i][2], s[i][3]));
            #pragma unroll
            for (int o = 1; o < 16; o <<= 1) mx = fmaxf(mx, __shfl_xor_sync(0xffffffffu, mx, o));
            float mnew = fmaxf(m_i[i], mx);
            float corr = __expf(m_i[i] - mnew);
            m_i[i] = mnew;
            float rs = 0.f;
            #pragma unroll
            for (int j = 0; j < 4; j++) { float p = __expf(s[i][j] - mnew); s[i][j] = p; rs += p; }
            #pragma unroll
            for (int o = 1; o < 16; o <<= 1) rs += __shfl_xor_sync(0xffffffffu, rs, o);
            l_i[i] = l_i[i] * corr + rs;
            #pragma unroll
            for (int j = 0; j < 4; j++) O[i][j] *= corr;
            *(float4*)&Ps[(ty * 4 + i) * 68 + (tx << 2)] = *(float4*)s[i];
        }
        __syncthreads();

        #pragma unroll 4
        for (int j = 0; j < 64; j++) {
            float4 vv = *(const float4*)&Vs[j * 68 + (tx << 2)];
            #pragma unroll
            for (int i = 0; i < 4; i++) {
                float p = Ps[(ty * 4 + i) * 68 + j];
                O[i][0] += p * vv.x; O[i][1] += p * vv.y;
                O[i][2] += p * vv.z; O[i][3] += p * vv.w;
            }
        }
    }

    float* obase = g_attn + ((size_t)b * T_ + qt * 64) * DM_ + h * DH_;
    #pragma unroll
    for (int i = 0; i < 4; i++) {
        float inv = 1.f / l_i[i];
        #pragma unroll
        for (int j = 0; j < 4; j++)
            obase[(size_t)(ty * 4 + i) * DM_ + (tx << 2) + j] = O[i][j] * inv;
    }
}

// ---------------- launch ----------------
extern "C" void kernel_launch(void* const* d_in, const int* in_sizes, int n_in,
                              void* d_out, int out_size) {
    const float* x     = (const float*)d_in[0];
    const float* w_dq  = (const float*)d_in[1];
    const float* w_uq  = (const float*)d_in[2];
    const float* w_rq  = (const float*)d_in[3];
    const float* w_dkv = (const float*)d_in[4];
    const float* w_rk  = (const float*)d_in[5];
    const float* w_uk  = (const float*)d_in[6];
    const float* w_uv  = (const float*)d_in[7];
    const float* w_o   = (const float*)d_in[8];
    float* out = (float*)d_out;

    float *cq, *ckv, *krot, *qstate, *qrot, *kstate, *vstate, *attn;
    cudaGetSymbolAddress((void**)&cq,     g_cq);
    cudaGetSymbolAddress((void**)&ckv,    g_ckv);
    cudaGetSymbolAddress((void**)&krot,   g_krot);
    cudaGetSymbolAddress((void**)&qstate, g_qstate);
    cudaGetSymbolAddress((void**)&qrot,   g_qrot);
    cudaGetSymbolAddress((void**)&kstate, g_kstate);
    cudaGetSymbolAddress((void**)&vstate, g_vstate);
    cudaGetSymbolAddress((void**)&attn,   g_attn);

    #define GRID(N) dim3(((N) + 127) / 128, BT_ / 128)
    gemm_tf32<<<GRID(DC1_),     256>>>(x,   w_dq,  cq,     BT_, DC1_,     DM_);
    gemm_tf32<<<GRID(DC_),      256>>>(x,   w_dkv, ckv,    BT_, DC_,      DM_);
    gemm_tf32<<<GRID(DR_),      256>>>(x,   w_rk,  krot,   BT_, DR_,      DM_);
    gemm_tf32<<<GRID(DM_),      256>>>(cq,  w_uq,  qstate, BT_, DM_,      DC1_);
    gemm_tf32<<<GRID(H_ * DR_), 256>>>(cq,  w_rq,  qrot,   BT_, H_ * DR_, DC1_);
    gemm_tf32<<<GRID(DM_),      256>>>(ckv, w_uk,  kstate, BT_, DM_,      DC_);
    gemm_tf32<<<GRID(DM_),      256>>>(ckv, w_uv,  vstate, BT_, DM_,      DC_);

    build_qk_kernel<<<BT_ * H_, 96>>>();

    cudaFuncSetAttribute(flash_kernel, cudaFuncAttributeMaxDynamicSharedMemorySize, FLASH_SMEM);
    flash_kernel<<<dim3(T_ / 64, H_, B_), 256, FLASH_SMEM>>>();

    gemm_tf32<<<GRID(DM_), 256>>>(attn, w_o, out, BT_, DM_, DM_);
    #undef GRID
}

// round 4
// speedup vs baseline: 2.3152x; 1.6463x over previous
#include <cuda_runtime.h>
#include <cuda_bf16.h>
#include <stdint.h>
#include <math.h>

#define B_   2
#define T_   2048
#define BT_  (B_*T_)
#define DM_  1024
#define H_   16
#define DH_  64
#define DC1_ 384
#define DC_  256
#define DR_  32
#define DQK_ 96

// ---------------- scratch (device globals: alloc-free) ----------------
__device__ float g_cq    [BT_*DC1_];
__device__ float g_ckv   [BT_*DC_];
__device__ float g_krot  [BT_*DR_];
__device__ float g_qstate[BT_*DM_];
__device__ float g_qrot  [BT_*H_*DR_];
__device__ float g_kstate[BT_*DM_];
__device__ float g_vstate[BT_*DM_];
__device__ float g_attn  [BT_*DM_];
// pre-split bf16 hi/lo q_final (scale folded) and k_final: layout [bt][h][96]
__device__ __nv_bfloat16 g_qh[BT_*H_*DQK_];
__device__ __nv_bfloat16 g_ql[BT_*H_*DQK_];
__device__ __nv_bfloat16 g_kh[BT_*H_*DQK_];
__device__ __nv_bfloat16 g_kl[BT_*H_*DQK_];

// ---------------- TF32 tensor-core GEMM: C[M,N] = A[M,K] @ B[K,N] ----------------
__device__ __forceinline__ unsigned f2tf(float f) {
    unsigned u; asm("cvt.rna.tf32.f32 %0, %1;" : "=r"(u) : "f"(f)); return u;
}

__device__ __forceinline__ void mma_tf32(float* c, const unsigned* a, const unsigned* b) {
    asm volatile(
        "mma.sync.aligned.m16n8k8.row.col.f32.tf32.tf32.f32 "
        "{%0,%1,%2,%3}, {%4,%5,%6,%7}, {%8,%9}, {%0,%1,%2,%3};"
        : "+f"(c[0]), "+f"(c[1]), "+f"(c[2]), "+f"(c[3])
        : "r"(a[0]), "r"(a[1]), "r"(a[2]), "r"(a[3]), "r"(b[0]), "r"(b[1]));
}

__global__ __launch_bounds__(256) void gemm_tf32(
        const float* __restrict__ A, const float* __restrict__ Bm,
        float* __restrict__ C, int M, int N, int K) {
    __shared__ float As[2][128][20];
    __shared__ float Bs[2][16][136];

    const int tid  = threadIdx.x;
    const int lane = tid & 31, warp = tid >> 5;
    const int gr = lane >> 2, tg = lane & 3;
    const int m0 = blockIdx.y << 7;
    const int n0 = blockIdx.x << 7;
    const int wm = (warp >> 2) << 6;
    const int wn = (warp & 3) << 5;

    float acc[4][4][4];
    #pragma unroll
    for (int i = 0; i < 4; i++)
        #pragma unroll
        for (int j = 0; j < 4; j++)
            #pragma unroll
            for (int r = 0; r < 4; r++) acc[i][j][r] = 0.f;

    #define LOAD_STAGE(BUF, K0)                                                       \
    {                                                                                 \
        _Pragma("unroll")                                                             \
        for (int u = 0; u < 2; u++) {                                                 \
            int idx = tid + (u << 8);                                                 \
            int r = idx >> 2, kq = (idx & 3) << 2;                                    \
            unsigned d = (unsigned)__cvta_generic_to_shared(&As[BUF][r][kq]);         \
            const float* s = A + (size_t)(m0 + r) * K + (K0) + kq;                    \
            asm volatile("cp.async.ca.shared.global [%0], [%1], 16;\n"                \
                         :: "r"(d), "l"(s));                                          \
        }                                                                             \
        _Pragma("unroll")                                                             \
        for (int u = 0; u < 2; u++) {                                                 \
            int idx = tid + (u << 8);                                                 \
            int r = idx >> 5, nq = (idx & 31) << 2;                                   \
            unsigned d = (unsigned)__cvta_generic_to_shared(&Bs[BUF][r][nq]);         \
            const float* s = Bm + (size_t)((K0) + r) * N + n0 + nq;                   \
            int sz = (n0 + nq < N) ? 16 : 0;                                          \
            asm volatile("cp.async.ca.shared.global [%0], [%1], 16, %2;\n"            \
                         :: "r"(d), "l"(s), "r"(sz));                                 \
        }                                                                             \
        asm volatile("cp.async.commit_group;\n");                                     \
    }

    int buf = 0;
    LOAD_STAGE(0, 0);

    for (int k0 = 0; k0 < K; k0 += 16) {
        if (k0 + 16 < K) {
            LOAD_STAGE(buf ^ 1, k0 + 16);
            asm volatile("cp.async.wait_group 1;\n");
        } else {
            asm volatile("cp.async.wait_group 0;\n");
        }
        __syncthreads();

        #pragma unroll
        for (int kk = 0; kk < 16; kk += 8) {
            unsigned af[4][4], bf[4][2];
            #pragma unroll
            for (int mt = 0; mt < 4; mt++) {
                int m = wm + (mt << 4);
                af[mt][0] = f2tf(As[buf][m + gr    ][kk + tg    ]);
                af[mt][1] = f2tf(As[buf][m + gr + 8][kk + tg    ]);
                af[mt][2] = f2tf(As[buf][m + gr    ][kk + tg + 4]);
                af[mt][3] = f2tf(As[buf][m + gr + 8][kk + tg + 4]);
            }
            #pragma unroll
            for (int nt = 0; nt < 4; nt++) {
                int n = wn + (nt << 3);
                bf[nt][0] = f2tf(Bs[buf][kk + tg    ][n + gr]);
                bf[nt][1] = f2tf(Bs[buf][kk + tg + 4][n + gr]);
            }
            #pragma unroll
            for (int mt = 0; mt < 4; mt++)
                #pragma unroll
                for (int nt = 0; nt < 4; nt++)
                    mma_tf32(acc[mt][nt], af[mt], bf[nt]);
        }
        __syncthreads();
        buf ^= 1;
    }
    #undef LOAD_STAGE

    #pragma unroll
    for (int mt = 0; mt < 4; mt++) {
        #pragma unroll
        for (int nt = 0; nt < 4; nt++) {
            int m = m0 + wm + (mt << 4) + gr;
            int n = n0 + wn + (nt << 3) + (tg << 1);
            if (n < N) {
                *(float2*)&C[(size_t)m * N + n]       = make_float2(acc[mt][nt][0], acc[mt][nt][1]);
                *(float2*)&C[(size_t)(m + 8) * N + n] = make_float2(acc[mt][nt][2], acc[mt][nt][3]);
            }
        }
    }
}

// ---------------- RoPE + concat + RMS-norm → pre-split bf16 q/k ----------------
__global__ void build_qk_kernel() {
    const int blk = blockIdx.x;           // bt*H + h
    const int bt  = blk >> 4;
    const int h   = blk & 15;
    const int t   = bt & (T_ - 1);
    const int d   = threadIdx.x;          // 0..95

    float qv, kv;
    if (d < DH_) {
        qv = g_qstate[(size_t)bt * DM_ + h * DH_ + d];
        kv = g_kstate[(size_t)bt * DM_ + h * DH_ + d];
    } else {
        const int dr = d - DH_;
        const int j  = dr & 15;
        float inv = powf(10000.f, -(float)j * (1.f / 16.f));
        float ang = (float)t * inv;
        float c = cosf(ang), sn = sinf(ang);
        const float* qr = g_qrot + (size_t)bt * (H_ * DR_) + h * DR_;
        const float* kr = g_krot + (size_t)bt * DR_;
        float x1 = qr[j], x2 = qr[16 + j];
        float y1 = kr[j], y2 = kr[16 + j];
        if (dr < 16) { qv = x1 * c - x2 * sn;  kv = y1 * c - y2 * sn; }
        else         { qv = x1 * sn + x2 * c;  kv = y1 * sn + y2 * c; }
    }
    float q2 = qv * qv, k2 = kv * kv;
    #pragma unroll
    for (int o = 16; o > 0; o >>= 1) {
        q2 += __shfl_xor_sync(0xffffffffu, q2, o);
        k2 += __shfl_xor_sync(0xffffffffu, k2, o);
    }
    __shared__ float pq[3], pk[3];
    const int w = d >> 5;
    if ((d & 31) == 0) { pq[w] = q2; pk[w] = k2; }
    __syncthreads();
    float sq = pq[0] + pq[1] + pq[2];
    float sk = pk[0] + pk[1] + pk[2];
    float rq = rsqrtf(sq * (1.f / 96.f) + 1e-6f);
    float rk = rsqrtf(sk * (1.f / 96.f) + 1e-6f);

    const float scale = 0.10206207261596577f;     // 1/sqrt(96), folded into q
    float qs = qv * rq * scale;
    float ks = kv * rk;
    __nv_bfloat16 qh = __float2bfloat16(qs);
    __nv_bfloat16 kh = __float2bfloat16(ks);
    size_t o = (size_t)blk * DQK_ + d;
    g_qh[o] = qh; g_ql[o] = __float2bfloat16(qs - __bfloat162float(qh));
    g_kh[o] = kh; g_kl[o] = __float2bfloat16(ks - __bfloat162float(kh));
}

// ---------------- flash attention, bf16x3 tensor cores ----------------
__device__ __forceinline__ void mma_bf16(float* c, const unsigned* a, const unsigned* b) {
    asm volatile(
        "mma.sync.aligned.m16n8k16.row.col.f32.bf16.bf16.f32 "
        "{%0,%1,%2,%3}, {%4,%5,%6,%7}, {%8,%9}, {%0,%1,%2,%3};"
        : "+f"(c[0]), "+f"(c[1]), "+f"(c[2]), "+f"(c[3])
        : "r"(a[0]), "r"(a[1]), "r"(a[2]), "r"(a[3]), "r"(b[0]), "r"(b[1]));
}

__device__ __forceinline__ unsigned packbf(float lo, float hi) {
    unsigned r; asm("cvt.rn.bf16x2.f32 %0, %1, %2;" : "=r"(r) : "f"(hi), "f"(lo));
    return r;
}
__device__ __forceinline__ void splitpack(float x0, float x1, unsigned& h, unsigned& l) {
    h = packbf(x0, x1);
    float h0 = __uint_as_float(h << 16);
    float h1 = __uint_as_float(h & 0xffff0000u);
    l = packbf(x0 - h0, x1 - h1);
}
__device__ __forceinline__ void cpa16(void* dst, const void* src) {
    unsigned d = (unsigned)__cvta_generic_to_shared(dst);
    asm volatile("cp.async.ca.shared.global [%0], [%1], 16;\n" :: "r"(d), "l"(src));
}

// smem (bf16 elems): Qh[64][104] Ql Kh[64][104] Kl | Vth[64][72] Vtl
#define QLD 104
#define VLD 72
#define OFF_QL  (64*QLD)
#define OFF_KH  (2*64*QLD)
#define OFF_KL  (3*64*QLD)
#define OFF_VTH (4*64*QLD)
#define OFF_VTL (4*64*QLD + 64*VLD)
#define FL_SMEM ((4*64*QLD + 2*64*VLD) * 2)

__global__ __launch_bounds__(128) void flash2() {
    extern __shared__ __nv_bfloat16 sb[];
    __nv_bfloat16* Qh  = sb;
    __nv_bfloat16* Ql  = sb + OFF_QL;
    __nv_bfloat16* Kh  = sb + OFF_KH;
    __nv_bfloat16* Kl  = sb + OFF_KL;
    __nv_bfloat16* Vth = sb + OFF_VTH;
    __nv_bfloat16* Vtl = sb + OFF_VTL;

    const int qt = gridDim.x - 1 - blockIdx.x;   // heavy tiles first
    const int h  = blockIdx.y;
    const int b  = blockIdx.z;
    const int tid = threadIdx.x, lane = tid & 31, w = tid >> 5;
    const int gr = lane >> 2, tg = lane & 3;

    // Q tile (64 rows x 96) cp.async, hi+lo
    {
        const __nv_bfloat16* qhg = g_qh + ((size_t)(b * T_ + qt * 64) * H_ + h) * DQK_;
        const __nv_bfloat16* qlg = g_ql + ((size_t)(b * T_ + qt * 64) * H_ + h) * DQK_;
        for (int i = tid; i < 64 * 12; i += 128) {
            int r = i / 12, c = i % 12;
            cpa16(&Qh[r * QLD + c * 8], qhg + (size_t)r * (H_ * DQK_) + c * 8);
            cpa16(&Ql[r * QLD + c * 8], qlg + (size_t)r * (H_ * DQK_) + c * 8);
        }
        asm volatile("cp.async.commit_group;\n");
    }

    float m_[2] = {-1e30f, -1e30f}, l_[2] = {0.f, 0.f};
    float O[8][4];
    #pragma unroll
    for (int nt = 0; nt < 8; nt++)
        #pragma unroll
        for (int j = 0; j < 4; j++) O[nt][j] = 0.f;

    for (int kt = 0; kt <= qt; kt++) {
        __syncthreads();   // prior iteration's smem reads finished
        // K tile cp.async
        {
            const __nv_bfloat16* khg = g_kh + ((size_t)(b * T_ + kt * 64) * H_ + h) * DQK_;
            const __nv_bfloat16* klg = g_kl + ((size_t)(b * T_ + kt * 64) * H_ + h) * DQK_;
            for (int i = tid; i < 64 * 12; i += 128) {
                int r = i / 12, c = i % 12;
                cpa16(&Kh[r * QLD + c * 8], khg + (size_t)r * (H_ * DQK_) + c * 8);
                cpa16(&Kl[r * QLD + c * 8], klg + (size_t)r * (H_ * DQK_) + c * 8);
            }
            asm volatile("cp.async.commit_group;\n");
        }
        // V tile: f32 gmem -> transposed bf16 hi/lo smem
        {
            const float* vg = g_vstate + (size_t)(b * T_ + kt * 64) * DM_ + h * DH_;
            for (int i = tid; i < 64 * 16; i += 128) {
                int r = i >> 4, c4 = i & 15;
                float4 v = *(const float4*)(vg + (size_t)r * DM_ + (c4 << 2));
                float xs[4] = {v.x, v.y, v.z, v.w};
                #pragma unroll
                for (int u = 0; u < 4; u++) {
                    int dd = c4 * 4 + u;
                    __nv_bfloat16 hb = __float2bfloat16(xs[u]);
                    Vth[dd * VLD + r] = hb;
                    Vtl[dd * VLD + r] = __float2bfloat16(xs[u] - __bfloat162float(hb));
                }
            }
        }
        asm volatile("cp.async.wait_group 0;\n");
        __syncthreads();

        // ---- S = Q @ K^T (bf16x3) ----
        float s[8][4];
        #pragma unroll
        for (int nt = 0; nt < 8; nt++)
            #pragma unroll
            for (int j = 0; j < 4; j++) s[nt][j] = 0.f;

        #pragma unroll
        for (int ks = 0; ks < 6; ks++) {
            const int qrow = w * 16 + gr, qc = ks * 16 + 2 * tg;
            unsigned ah[4], al[4];
            ah[0] = *(const unsigned*)&Qh[qrow * QLD + qc];
            ah[1] = *(const unsigned*)&Qh[(qrow + 8) * QLD + qc];
            ah[2] = *(const unsigned*)&Qh[qrow * QLD + qc + 8];
            ah[3] = *(const unsigned*)&Qh[(qrow + 8) * QLD + qc + 8];
            al[0] = *(const unsigned*)&Ql[qrow * QLD + qc];
            al[1] = *(const unsigned*)&Ql[(qrow + 8) * QLD + qc];
            al[2] = *(const unsigned*)&Ql[qrow * QLD + qc + 8];
            al[3] = *(const unsigned*)&Ql[(qrow + 8) * QLD + qc + 8];
            #pragma unroll
            for (int nt = 0; nt < 8; nt++) {
                const int krow = nt * 8 + gr;
                unsigned bh[2], bl[2];
                bh[0] = *(const unsigned*)&Kh[krow * QLD + qc];
                bh[1] = *(const unsigned*)&Kh[krow * QLD + qc + 8];
                bl[0] = *(const unsigned*)&Kl[krow * QLD + qc];
                bl[1] = *(const unsigned*)&Kl[krow * QLD + qc + 8];
                mma_bf16(s[nt], ah, bh);
                mma_bf16(s[nt], ah, bl);
                mma_bf16(s[nt], al, bh);
            }
        }

        if (kt == qt) {
            const int rowA = w * 16 + gr, rowB = rowA + 8;
            #pragma unroll
            for (int nt = 0; nt < 8; nt++) {
                int cb = nt * 8 + 2 * tg;
                if (cb     > rowA) s[nt][0] = -1e30f;
                if (cb + 1 > rowA) s[nt][1] = -1e30f;
                if (cb     > rowB) s[nt][2] = -1e30f;
                if (cb + 1 > rowB) s[nt][3] = -1e30f;
            }
        }

        // ---- online softmax (rows gr, gr+8; quad = lanes sharing gr) ----
        float mA = -1e30f, mB = -1e30f;
        #pragma unroll
        for (int nt = 0; nt < 8; nt++) {
            mA = fmaxf(mA, fmaxf(s[nt][0], s[nt][1]));
            mB = fmaxf(mB, fmaxf(s[nt][2], s[nt][3]));
        }
        mA = fmaxf(mA, __shfl_xor_sync(0xffffffffu, mA, 1));
        mA = fmaxf(mA, __shfl_xor_sync(0xffffffffu, mA, 2));
        mB = fmaxf(mB, __shfl_xor_sync(0xffffffffu, mB, 1));
        mB = fmaxf(mB, __shfl_xor_sync(0xffffffffu, mB, 2));
        float nA = fmaxf(m_[0], mA), nB = fmaxf(m_[1], mB);
        float cA = __expf(m_[0] - nA), cB = __expf(m_[1] - nB);
        m_[0] = nA; m_[1] = nB;
        float rA = 0.f, rB = 0.f;
        #pragma unroll
        for (int nt = 0; nt < 8; nt++) {
            s[nt][0] = __expf(s[nt][0] - nA);
            s[nt][1] = __expf(s[nt][1] - nA);
            s[nt][2] = __expf(s[nt][2] - nB);
            s[nt][3] = __expf(s[nt][3] - nB);
            rA += s[nt][0] + s[nt][1];
            rB += s[nt][2] + s[nt][3];
            O[nt][0] *= cA; O[nt][1] *= cA;
            O[nt][2] *= cB; O[nt][3] *= cB;
        }
        rA += __shfl_xor_sync(0xffffffffu, rA, 1);
        rA += __shfl_xor_sync(0xffffffffu, rA, 2);
        rB += __shfl_xor_sync(0xffffffffu, rB, 1);
        rB += __shfl_xor_sync(0xffffffffu, rB, 2);
        l_[0] = l_[0] * cA + rA;
        l_[1] = l_[1] * cB + rB;

        // ---- O += P @ V (bf16x3; P frags straight from S registers) ----
        #pragma unroll
        for (int kk = 0; kk < 4; kk++) {
            unsigned ah[4], al[4];
            splitpack(s[2*kk    ][0], s[2*kk    ][1], ah[0], al[0]);
            splitpack(s[2*kk    ][2], s[2*kk    ][3], ah[1], al[1]);
            splitpack(s[2*kk + 1][0], s[2*kk + 1][1], ah[2], al[2]);
            splitpack(s[2*kk + 1][2], s[2*kk + 1][3], ah[3], al[3]);
            #pragma unroll
            for (int nt = 0; nt < 8; nt++) {
                const int vrow = nt * 8 + gr;
                const int vc = kk * 16 + 2 * tg;
                unsigned bh[2], bl[2];
                bh[0] = *(const unsigned*)&Vth[vrow * VLD + vc];
                bh[1] = *(const unsigned*)&Vth[vrow * VLD + vc + 8];
                bl[0] = *(const unsigned*)&Vtl[vrow * VLD + vc];
                bl[1] = *(const unsigned*)&Vtl[vrow * VLD + vc + 8];
                mma_bf16(O[nt], ah, bh);
                mma_bf16(O[nt], ah, bl);
                mma_bf16(O[nt], al, bh);
            }
        }
    }

    // epilogue
    float iA = 1.f / l_[0], iB = 1.f / l_[1];
    float* ob = g_attn + (size_t)(b * T_ + qt * 64) * DM_ + h * DH_;
    const int rowA = w * 16 + gr;
    #pragma unroll
    for (int nt = 0; nt < 8; nt++) {
        int col = nt * 8 + 2 * tg;
        *(float2*)&ob[(size_t)rowA * DM_ + col] =
            make_float2(O[nt][0] * iA, O[nt][1] * iA);
        *(float2*)&ob[(size_t)(rowA + 8) * DM_ + col] =
            make_float2(O[nt][2] * iB, O[nt][3] * iB);
    }
}

// ---------------- launch ----------------
extern "C" void kernel_launch(void* const* d_in, const int* in_sizes, int n_in,
                              void* d_out, int out_size) {
    const float* x     = (const float*)d_in[0];
    const float* w_dq  = (const float*)d_in[1];
    const float* w_uq  = (const float*)d_in[2];
    const float* w_rq  = (const float*)d_in[3];
    const float* w_dkv = (const float*)d_in[4];
    const float* w_rk  = (const float*)d_in[5];
    const float* w_uk  = (const float*)d_in[6];
    const float* w_uv  = (const float*)d_in[7];
    const float* w_o   = (const float*)d_in[8];
    float* out = (float*)d_out;

    float *cq, *ckv, *krot, *qstate, *qrot, *kstate, *vstate, *attn;
    cudaGetSymbolAddress((void**)&cq,     g_cq);
    cudaGetSymbolAddress((void**)&ckv,    g_ckv);
    cudaGetSymbolAddress((void**)&krot,   g_krot);
    cudaGetSymbolAddress((void**)&qstate, g_qstate);
    cudaGetSymbolAddress((void**)&qrot,   g_qrot);
    cudaGetSymbolAddress((void**)&kstate, g_kstate);
    cudaGetSymbolAddress((void**)&vstate, g_vstate);
    cudaGetSymbolAddress((void**)&attn,   g_attn);

    #define GRID(N) dim3(((N) + 127) / 128, BT_ / 128)
    gemm_tf32<<<GRID(DC1_),     256>>>(x,   w_dq,  cq,     BT_, DC1_,     DM_);
    gemm_tf32<<<GRID(DC_),      256>>>(x,   w_dkv, ckv,    BT_, DC_,      DM_);
    gemm_tf32<<<GRID(DR_),      256>>>(x,   w_rk,  krot,   BT_, DR_,      DM_);
    gemm_tf32<<<GRID(DM_),      256>>>(cq,  w_uq,  qstate, BT_, DM_,      DC1_);
    gemm_tf32<<<GRID(H_ * DR_), 256>>>(cq,  w_rq,  qrot,   BT_, H_ * DR_, DC1_);
    gemm_tf32<<<GRID(DM_),      256>>>(ckv, w_uk,  kstate, BT_, DM_,      DC_);
    gemm_tf32<<<GRID(DM_),      256>>>(ckv, w_uv,  vstate, BT_, DM_,      DC_);

    build_qk_kernel<<<BT_ * H_, 96>>>();

    cudaFuncSetAttribute(flash2, cudaFuncAttributeMaxDynamicSharedMemorySize, FL_SMEM);
    flash2<<<dim3(T_ / 64, H_, B_), 128, FL_SMEM>>>();

    gemm_tf32<<<GRID(DM_), 256>>>(attn, w_o, out, BT_, DM_, DM_);
    #undef GRID
}

// round 5
// speedup vs baseline: 2.9117x; 1.2576x over previous
#include <cuda_runtime.h>
#include <cuda_bf16.h>
#include <stdint.h>
#include <math.h>

#define B_   2
#define T_   2048
#define BT_  (B_*T_)
#define DM_  1024
#define H_   16
#define DH_  64
#define DC1_ 384
#define DC_  256
#define DR_  32
#define DQK_ 96

// ---------------- scratch (device globals: alloc-free) ----------------
__device__ float g_cq    [BT_*DC1_];
__device__ float g_ckv   [BT_*DC_];
__device__ float g_krot  [BT_*DR_];
__device__ float g_qstate[BT_*DM_];
__device__ float g_qrot  [BT_*H_*DR_];
__device__ float g_kstate[BT_*DM_];
__device__ float g_vstate[BT_*DM_];
__device__ float g_attn  [BT_*DM_];
// pre-split bf16 hi/lo q_final (scale folded) and k_final: [bt][h][96]
__device__ __nv_bfloat16 g_qh[BT_*H_*DQK_];
__device__ __nv_bfloat16 g_ql[BT_*H_*DQK_];
__device__ __nv_bfloat16 g_kh[BT_*H_*DQK_];
__device__ __nv_bfloat16 g_kl[BT_*H_*DQK_];
// pre-split, pre-transposed V: [b][h][d=64][t=2048]
__device__ __nv_bfloat16 g_vth[B_*H_*DH_*T_];
__device__ __nv_bfloat16 g_vtl[B_*H_*DH_*T_];

// ---------------- TF32 tensor-core GEMM: C[M,N] = A[M,K] @ B[K,N] ----------------
__device__ __forceinline__ unsigned f2tf(float f) {
    unsigned u; asm("cvt.rna.tf32.f32 %0, %1;" : "=r"(u) : "f"(f)); return u;
}

__device__ __forceinline__ void mma_tf32(float* c, const unsigned* a, const unsigned* b) {
    asm volatile(
        "mma.sync.aligned.m16n8k8.row.col.f32.tf32.tf32.f32 "
        "{%0,%1,%2,%3}, {%4,%5,%6,%7}, {%8,%9}, {%0,%1,%2,%3};"
        : "+f"(c[0]), "+f"(c[1]), "+f"(c[2]), "+f"(c[3])
        : "r"(a[0]), "r"(a[1]), "r"(a[2]), "r"(a[3]), "r"(b[0]), "r"(b[1]));
}

__global__ __launch_bounds__(256) void gemm_tf32(
        const float* __restrict__ A, const float* __restrict__ Bm,
        float* __restrict__ C, int M, int N, int K) {
    __shared__ float As[2][128][20];
    __shared__ float Bs[2][16][136];

    const int tid  = threadIdx.x;
    const int lane = tid & 31, warp = tid >> 5;
    const int gr = lane >> 2, tg = lane & 3;
    const int m0 = blockIdx.y << 7;
    const int n0 = blockIdx.x << 7;
    const int wm = (warp >> 2) << 6;
    const int wn = (warp & 3) << 5;

    float acc[4][4][4];
    #pragma unroll
    for (int i = 0; i < 4; i++)
        #pragma unroll
        for (int j = 0; j < 4; j++)
            #pragma unroll
            for (int r = 0; r < 4; r++) acc[i][j][r] = 0.f;

    #define LOAD_STAGE(BUF, K0)                                                       \
    {                                                                                 \
        _Pragma("unroll")                                                             \
        for (int u = 0; u < 2; u++) {                                                 \
            int idx = tid + (u << 8);                                                 \
            int r = idx >> 2, kq = (idx & 3) << 2;                                    \
            unsigned d = (unsigned)__cvta_generic_to_shared(&As[BUF][r][kq]);         \
            const float* s = A + (size_t)(m0 + r) * K + (K0) + kq;                    \
            asm volatile("cp.async.ca.shared.global [%0], [%1], 16;\n"                \
                         :: "r"(d), "l"(s));                                          \
        }                                                                             \
        _Pragma("unroll")                                                             \
        for (int u = 0; u < 2; u++) {                                                 \
            int idx = tid + (u << 8);                                                 \
            int r = idx >> 5, nq = (idx & 31) << 2;                                   \
            unsigned d = (unsigned)__cvta_generic_to_shared(&Bs[BUF][r][nq]);         \
            const float* s = Bm + (size_t)((K0) + r) * N + n0 + nq;                   \
            int sz = (n0 + nq < N) ? 16 : 0;                                          \
            asm volatile("cp.async.ca.shared.global [%0], [%1], 16, %2;\n"            \
                         :: "r"(d), "l"(s), "r"(sz));                                 \
        }                                                                             \
        asm volatile("cp.async.commit_group;\n");                                     \
    }

    int buf = 0;
    LOAD_STAGE(0, 0);

    for (int k0 = 0; k0 < K; k0 += 16) {
        if (k0 + 16 < K) {
            LOAD_STAGE(buf ^ 1, k0 + 16);
            asm volatile("cp.async.wait_group 1;\n");
        } else {
            asm volatile("cp.async.wait_group 0;\n");
        }
        __syncthreads();

        #pragma unroll
        for (int kk = 0; kk < 16; kk += 8) {
            unsigned af[4][4], bf[4][2];
            #pragma unroll
            for (int mt = 0; mt < 4; mt++) {
                int m = wm + (mt << 4);
                af[mt][0] = f2tf(As[buf][m + gr    ][kk + tg    ]);
                af[mt][1] = f2tf(As[buf][m + gr + 8][kk + tg    ]);
                af[mt][2] = f2tf(As[buf][m + gr    ][kk + tg + 4]);
                af[mt][3] = f2tf(As[buf][m + gr + 8][kk + tg + 4]);
            }
            #pragma unroll
            for (int nt = 0; nt < 4; nt++) {
                int n = wn + (nt << 3);
                bf[nt][0] = f2tf(Bs[buf][kk + tg    ][n + gr]);
                bf[nt][1] = f2tf(Bs[buf][kk + tg + 4][n + gr]);
            }
            #pragma unroll
            for (int mt = 0; mt < 4; mt++)
                #pragma unroll
                for (int nt = 0; nt < 4; nt++)
                    mma_tf32(acc[mt][nt], af[mt], bf[nt]);
        }
        __syncthreads();
        buf ^= 1;
    }
    #undef LOAD_STAGE

    #pragma unroll
    for (int mt = 0; mt < 4; mt++) {
        #pragma unroll
        for (int nt = 0; nt < 4; nt++) {
            int m = m0 + wm + (mt << 4) + gr;
            int n = n0 + wn + (nt << 3) + (tg << 1);
            if (n < N) {
                *(float2*)&C[(size_t)m * N + n]       = make_float2(acc[mt][nt][0], acc[mt][nt][1]);
                *(float2*)&C[(size_t)(m + 8) * N + n] = make_float2(acc[mt][nt][2], acc[mt][nt][3]);
            }
        }
    }
}

// ---------------- RoPE + concat + RMS-norm → pre-split bf16 q/k ----------------
__global__ void build_qk_kernel() {
    const int blk = blockIdx.x;           // bt*H + h
    const int bt  = blk >> 4;
    const int h   = blk & 15;
    const int t   = bt & (T_ - 1);
    const int d   = threadIdx.x;          // 0..95

    float qv, kv;
    if (d < DH_) {
        qv = g_qstate[(size_t)bt * DM_ + h * DH_ + d];
        kv = g_kstate[(size_t)bt * DM_ + h * DH_ + d];
    } else {
        const int dr = d - DH_;
        const int j  = dr & 15;
        float inv = powf(10000.f, -(float)j * (1.f / 16.f));
        float ang = (float)t * inv;
        float c = cosf(ang), sn = sinf(ang);
        const float* qr = g_qrot + (size_t)bt * (H_ * DR_) + h * DR_;
        const float* kr = g_krot + (size_t)bt * DR_;
        float x1 = qr[j], x2 = qr[16 + j];
        float y1 = kr[j], y2 = kr[16 + j];
        if (dr < 16) { qv = x1 * c - x2 * sn;  kv = y1 * c - y2 * sn; }
        else         { qv = x1 * sn + x2 * c;  kv = y1 * sn + y2 * c; }
    }
    float q2 = qv * qv, k2 = kv * kv;
    #pragma unroll
    for (int o = 16; o > 0; o >>= 1) {
        q2 += __shfl_xor_sync(0xffffffffu, q2, o);
        k2 += __shfl_xor_sync(0xffffffffu, k2, o);
    }
    __shared__ float pq[3], pk[3];
    const int w = d >> 5;
    if ((d & 31) == 0) { pq[w] = q2; pk[w] = k2; }
    __syncthreads();
    float sq = pq[0] + pq[1] + pq[2];
    float sk = pk[0] + pk[1] + pk[2];
    float rq = rsqrtf(sq * (1.f / 96.f) + 1e-6f);
    float rk = rsqrtf(sk * (1.f / 96.f) + 1e-6f);

    const float scale = 0.10206207261596577f;     // 1/sqrt(96), folded into q
    float qs = qv * rq * scale;
    float ks = kv * rk;
    __nv_bfloat16 qh = __float2bfloat16(qs);
    __nv_bfloat16 kh = __float2bfloat16(ks);
    size_t o = (size_t)blk * DQK_ + d;
    g_qh[o] = qh; g_ql[o] = __float2bfloat16(qs - __bfloat162float(qh));
    g_kh[o] = kh; g_kl[o] = __float2bfloat16(ks - __bfloat162float(kh));
}

// ---------------- V pre-pass: fp32 [bt][h*64+d] -> bf16 hi/lo [b][h][d][t] ----------------
__global__ __launch_bounds__(256) void convert_v() {
    __shared__ float vs[64][65];
    const int tt = blockIdx.x * 64, h = blockIdx.y, b = blockIdx.z;
    const int tid = threadIdx.x;
    for (int i = tid; i < 64 * 16; i += 256) {
        int r = i >> 4, c4 = i & 15;
        float4 v = *(const float4*)(g_vstate + (size_t)(b * T_ + tt + r) * DM_ + h * DH_ + (c4 << 2));
        vs[r][c4 * 4 + 0] = v.x; vs[r][c4 * 4 + 1] = v.y;
        vs[r][c4 * 4 + 2] = v.z; vs[r][c4 * 4 + 3] = v.w;
    }
    __syncthreads();
    for (int i = tid; i < 64 * 64; i += 256) {
        int d = i >> 6, t = i & 63;
        float x = vs[t][d];
        __nv_bfloat16 hb = __float2bfloat16(x);
        size_t o = ((size_t)(b * H_ + h) * DH_ + d) * T_ + tt + t;
        g_vth[o] = hb;
        g_vtl[o] = __float2bfloat16(x - __bfloat162float(hb));
    }
}

// ---------------- flash attention v3: 128-row Q tiles, 8 warps, ldmatrix ----------------
__device__ __forceinline__ void mma_bf16(float* c, const unsigned* a, const unsigned* b) {
    asm volatile(
        "mma.sync.aligned.m16n8k16.row.col.f32.bf16.bf16.f32 "
        "{%0,%1,%2,%3}, {%4,%5,%6,%7}, {%8,%9}, {%0,%1,%2,%3};"
        : "+f"(c[0]), "+f"(c[1]), "+f"(c[2]), "+f"(c[3])
        : "r"(a[0]), "r"(a[1]), "r"(a[2]), "r"(a[3]), "r"(b[0]), "r"(b[1]));
}
__device__ __forceinline__ unsigned packbf(float lo, float hi) {
    unsigned r; asm("cvt.rn.bf16x2.f32 %0, %1, %2;" : "=r"(r) : "f"(hi), "f"(lo));
    return r;
}
__device__ __forceinline__ void splitpack(float x0, float x1, unsigned& h, unsigned& l) {
    h = packbf(x0, x1);
    float h0 = __uint_as_float(h << 16);
    float h1 = __uint_as_float(h & 0xffff0000u);
    l = packbf(x0 - h0, x1 - h1);
}
__device__ __forceinline__ void cpa16(void* dst, const void* src) {
    unsigned d = (unsigned)__cvta_generic_to_shared(dst);
    asm volatile("cp.async.ca.shared.global [%0], [%1], 16;\n" :: "r"(d), "l"(src));
}
__device__ __forceinline__ void ldm_x4(unsigned* r, const void* p) {
    unsigned a = (unsigned)__cvta_generic_to_shared(p);
    asm volatile("ldmatrix.sync.aligned.m8n8.x4.shared.b16 {%0,%1,%2,%3}, [%4];"
                 : "=r"(r[0]), "=r"(r[1]), "=r"(r[2]), "=r"(r[3]) : "r"(a));
}

#define QLD 104
#define VLD 72
#define OFF_QL  (128*QLD)
#define OFF_KH  (2*128*QLD)
#define OFF_KL  (OFF_KH + 64*QLD)
#define OFF_VTH (OFF_KH + 2*64*QLD)
#define OFF_VTL (OFF_VTH + 64*VLD)
#define FL_SMEM ((2*128*QLD + 2*64*QLD + 2*64*VLD) * 2)

__global__ __launch_bounds__(256) void flash3() {
    extern __shared__ __nv_bfloat16 sb[];
    __nv_bfloat16* Qh  = sb;
    __nv_bfloat16* Ql  = sb + OFF_QL;
    __nv_bfloat16* Kh  = sb + OFF_KH;
    __nv_bfloat16* Kl  = sb + OFF_KL;
    __nv_bfloat16* Vth = sb + OFF_VTH;
    __nv_bfloat16* Vtl = sb + OFF_VTL;

    const int qt = gridDim.x - 1 - blockIdx.x;   // heavy tiles first
    const int h  = blockIdx.y;
    const int b  = blockIdx.z;
    const int tid = threadIdx.x, lane = tid & 31, w = tid >> 5;
    const int gr = lane >> 2, tg = lane & 3;
    const int li = lane & 7, lsel = lane >> 3;

    // Q tile (128 rows x 96), hi+lo
    {
        const __nv_bfloat16* qhg = g_qh + ((size_t)(b * T_ + qt * 128) * H_ + h) * DQK_;
        const __nv_bfloat16* qlg = g_ql + ((size_t)(b * T_ + qt * 128) * H_ + h) * DQK_;
        for (int i = tid; i < 128 * 12; i += 256) {
            int r = i / 12, c = i % 12;
            cpa16(&Qh[r * QLD + c * 8], qhg + (size_t)r * (H_ * DQK_) + c * 8);
            cpa16(&Ql[r * QLD + c * 8], qlg + (size_t)r * (H_ * DQK_) + c * 8);
        }
        asm volatile("cp.async.commit_group;\n");
    }

    float m_[2] = {-1e30f, -1e30f}, l_[2] = {0.f, 0.f};
    float O[8][4];
    #pragma unroll
    for (int nt = 0; nt < 8; nt++)
        #pragma unroll
        for (int j = 0; j < 4; j++) O[nt][j] = 0.f;

    const int rowlo = qt * 128 + w * 16;    // warp's first global row
    const int ktmax = 2 * qt + 1;

    for (int kt = 0; kt <= ktmax; kt++) {
        __syncthreads();
        {
            const __nv_bfloat16* khg = g_kh + ((size_t)(b * T_ + kt * 64) * H_ + h) * DQK_;
            const __nv_bfloat16* klg = g_kl + ((size_t)(b * T_ + kt * 64) * H_ + h) * DQK_;
            for (int i = tid; i < 64 * 12; i += 256) {
                int r = i / 12, c = i % 12;
                cpa16(&Kh[r * QLD + c * 8], khg + (size_t)r * (H_ * DQK_) + c * 8);
                cpa16(&Kl[r * QLD + c * 8], klg + (size_t)r * (H_ * DQK_) + c * 8);
            }
            const __nv_bfloat16* vhg = g_vth + (size_t)(b * H_ + h) * DH_ * T_ + kt * 64;
            const __nv_bfloat16* vlg = g_vtl + (size_t)(b * H_ + h) * DH_ * T_ + kt * 64;
            for (int i = tid; i < 64 * 8; i += 256) {
                int d = i >> 3, c = i & 7;
                cpa16(&Vth[d * VLD + c * 8], vhg + (size_t)d * T_ + c * 8);
                cpa16(&Vtl[d * VLD + c * 8], vlg + (size_t)d * T_ + c * 8);
            }
            asm volatile("cp.async.commit_group;\n");
        }
        asm volatile("cp.async.wait_group 0;\n");
        __syncthreads();

        const bool active = (kt * 64 <= rowlo + 15);
        if (active) {
            // ---- S = Q @ K^T (bf16x3) ----
            float s[8][4];
            #pragma unroll
            for (int nt = 0; nt < 8; nt++)
                #pragma unroll
                for (int j = 0; j < 4; j++) s[nt][j] = 0.f;

            #pragma unroll
            for (int ks = 0; ks < 6; ks++) {
                unsigned ah[4], al[4];
                {
                    int r = w * 16 + ((lsel & 1) << 3) + li;
                    int c = ks * 16 + ((lsel >> 1) << 3);
                    ldm_x4(ah, &Qh[r * QLD + c]);
                    ldm_x4(al, &Ql[r * QLD + c]);
                }
                #pragma unroll
                for (int np = 0; np < 4; np++) {
                    unsigned bh[4], bl[4];
                    int r = np * 16 + ((lsel >> 1) << 3) + li;
                    int c = ks * 16 + ((lsel & 1) << 3);
                    ldm_x4(bh, &Kh[r * QLD + c]);
                    ldm_x4(bl, &Kl[r * QLD + c]);
                    mma_bf16(s[2*np    ], ah, &bh[0]);
                    mma_bf16(s[2*np    ], ah, &bl[0]);
                    mma_bf16(s[2*np    ], al, &bh[0]);
                    mma_bf16(s[2*np + 1], ah, &bh[2]);
                    mma_bf16(s[2*np + 1], ah, &bl[2]);
                    mma_bf16(s[2*np + 1], al, &bh[2]);
                }
            }

            // ---- causal mask (only when tile touches diagonal) ----
            if (kt * 64 + 63 > rowlo) {
                const int rowA = rowlo + gr, rowB = rowA + 8;
                #pragma unroll
                for (int nt = 0; nt < 8; nt++) {
                    int cb = kt * 64 + nt * 8 + 2 * tg;
                    if (cb     > rowA) s[nt][0] = -1e30f;
                    if (cb + 1 > rowA) s[nt][1] = -1e30f;
                    if (cb     > rowB) s[nt][2] = -1e30f;
                    if (cb + 1 > rowB) s[nt][3] = -1e30f;
                }
            }

            // ---- online softmax ----
            float mA = -1e30f, mB = -1e30f;
            #pragma unroll
            for (int nt = 0; nt < 8; nt++) {
                mA = fmaxf(mA, fmaxf(s[nt][0], s[nt][1]));
                mB = fmaxf(mB, fmaxf(s[nt][2], s[nt][3]));
            }
            mA = fmaxf(mA, __shfl_xor_sync(0xffffffffu, mA, 1));
            mA = fmaxf(mA, __shfl_xor_sync(0xffffffffu, mA, 2));
            mB = fmaxf(mB, __shfl_xor_sync(0xffffffffu, mB, 1));
            mB = fmaxf(mB, __shfl_xor_sync(0xffffffffu, mB, 2));
            float nA = fmaxf(m_[0], mA), nB = fmaxf(m_[1], mB);
            float cA = __expf(m_[0] - nA), cB = __expf(m_[1] - nB);
            m_[0] = nA; m_[1] = nB;
            float rA = 0.f, rB = 0.f;
            #pragma unroll
            for (int nt = 0; nt < 8; nt++) {
                s[nt][0] = __expf(s[nt][0] - nA);
                s[nt][1] = __expf(s[nt][1] - nA);
                s[nt][2] = __expf(s[nt][2] - nB);
                s[nt][3] = __expf(s[nt][3] - nB);
                rA += s[nt][0] + s[nt][1];
                rB += s[nt][2] + s[nt][3];
                O[nt][0] *= cA; O[nt][1] *= cA;
                O[nt][2] *= cB; O[nt][3] *= cB;
            }
            rA += __shfl_xor_sync(0xffffffffu, rA, 1);
            rA += __shfl_xor_sync(0xffffffffu, rA, 2);
            rB += __shfl_xor_sync(0xffffffffu, rB, 1);
            rB += __shfl_xor_sync(0xffffffffu, rB, 2);
            l_[0] = l_[0] * cA + rA;
            l_[1] = l_[1] * cB + rB;

            // ---- O += P @ V (bf16x3; P frags straight from S registers) ----
            #pragma unroll
            for (int kk = 0; kk < 4; kk++) {
                unsigned ah[4], al[4];
                splitpack(s[2*kk    ][0], s[2*kk    ][1], ah[0], al[0]);
                splitpack(s[2*kk    ][2], s[2*kk    ][3], ah[1], al[1]);
                splitpack(s[2*kk + 1][0], s[2*kk + 1][1], ah[2], al[2]);
                splitpack(s[2*kk + 1][2], s[2*kk + 1][3], ah[3], al[3]);
                #pragma unroll
                for (int np = 0; np < 4; np++) {
                    unsigned bh[4], bl[4];
                    int r = np * 16 + ((lsel >> 1) << 3) + li;
                    int c = kk * 16 + ((lsel & 1) << 3);
                    ldm_x4(bh, &Vth[r * VLD + c]);
                    ldm_x4(bl, &Vtl[r * VLD + c]);
                    mma_bf16(O[2*np    ], ah, &bh[0]);
                    mma_bf16(O[2*np    ], ah, &bl[0]);
                    mma_bf16(O[2*np    ], al, &bh[0]);
                    mma_bf16(O[2*np + 1], ah, &bh[2]);
                    mma_bf16(O[2*np + 1], ah, &bl[2]);
                    mma_bf16(O[2*np + 1], al, &bh[2]);
                }
            }
        }
    }

    // epilogue
    float iA = 1.f / l_[0], iB = 1.f / l_[1];
    float* ob = g_attn + (size_t)(b * T_ + qt * 128 + w * 16) * DM_ + h * DH_;
    #pragma unroll
    for (int nt = 0; nt < 8; nt++) {
        int col = nt * 8 + 2 * tg;
        *(float2*)&ob[(size_t)gr * DM_ + col] =
            make_float2(O[nt][0] * iA, O[nt][1] * iA);
        *(float2*)&ob[(size_t)(gr + 8) * DM_ + col] =
            make_float2(O[nt][2] * iB, O[nt][3] * iB);
    }
}

// ---------------- launch ----------------
extern "C" void kernel_launch(void* const* d_in, const int* in_sizes, int n_in,
                              void* d_out, int out_size) {
    const float* x     = (const float*)d_in[0];
    const float* w_dq  = (const float*)d_in[1];
    const float* w_uq  = (const float*)d_in[2];
    const float* w_rq  = (const float*)d_in[3];
    const float* w_dkv = (const float*)d_in[4];
    const float* w_rk  = (const float*)d_in[5];
    const float* w_uk  = (const float*)d_in[6];
    const float* w_uv  = (const float*)d_in[7];
    const float* w_o   = (const float*)d_in[8];
    float* out = (float*)d_out;

    float *cq, *ckv, *krot, *qstate, *qrot, *kstate, *vstate, *attn;
    cudaGetSymbolAddress((void**)&cq,     g_cq);
    cudaGetSymbolAddress((void**)&ckv,    g_ckv);
    cudaGetSymbolAddress((void**)&krot,   g_krot);
    cudaGetSymbolAddress((void**)&qstate, g_qstate);
    cudaGetSymbolAddress((void**)&qrot,   g_qrot);
    cudaGetSymbolAddress((void**)&kstate, g_kstate);
    cudaGetSymbolAddress((void**)&vstate, g_vstate);
    cudaGetSymbolAddress((void**)&attn,   g_attn);

    #define GRID(N) dim3(((N) + 127) / 128, BT_ / 128)
    gemm_tf32<<<GRID(DC1_),     256>>>(x,   w_dq,  cq,     BT_, DC1_,     DM_);
    gemm_tf32<<<GRID(DC_),      256>>>(x,   w_dkv, ckv,    BT_, DC_,      DM_);
    gemm_tf32<<<GRID(DR_),      256>>>(x,   w_rk,  krot,   BT_, DR_,      DM_);
    gemm_tf32<<<GRID(DM_),      256>>>(cq,  w_uq,  qstate, BT_, DM_,      DC1_);
    gemm_tf32<<<GRID(H_ * DR_), 256>>>(cq,  w_rq,  qrot,   BT_, H_ * DR_, DC1_);
    gemm_tf32<<<GRID(DM_),      256>>>(ckv, w_uk,  kstate, BT_, DM_,      DC_);
    gemm_tf32<<<GRID(DM_),      256>>>(ckv, w_uv,  vstate, BT_, DM_,      DC_);

    build_qk_kernel<<<BT_ * H_, 96>>>();
    convert_v<<<dim3(T_ / 64, H_, B_), 256>>>();

    cudaFuncSetAttribute(flash3, cudaFuncAttributeMaxDynamicSharedMemorySize, FL_SMEM);
    flash3<<<dim3(T_ / 128, H_, B_), 256, FL_SMEM>>>();

    gemm_tf32<<<GRID(DM_), 256>>>(attn, w_o, out, BT_, DM_, DM_);
    #undef GRID
}

// round 6
// speedup vs baseline: 3.0803x; 1.0579x over previous
#include <cuda_runtime.h>
#include <cuda_bf16.h>
#include <stdint.h>
#include <math.h>

#define B_   2
#define T_   2048
#define BT_  (B_*T_)
#define DM_  1024
#define H_   16
#define DH_  64
#define DC1_ 384
#define DC_  256
#define DR_  32
#define DQK_ 96

// ---------------- scratch (device globals: alloc-free) ----------------
__device__ float g_cq    [BT_*DC1_];
__device__ float g_ckv   [BT_*DC_];
__device__ float g_krot  [BT_*DR_];
__device__ float g_qstate[BT_*DM_];
__device__ float g_qrot  [BT_*H_*DR_];
__device__ float g_kstate[BT_*DM_];
__device__ float g_vstate[BT_*DM_];
__device__ float g_attn  [BT_*DM_];
// pre-split bf16 hi/lo q_final (scale folded) and k_final: [bt][h][96]
__device__ __nv_bfloat16 g_qh[BT_*H_*DQK_];
__device__ __nv_bfloat16 g_ql[BT_*H_*DQK_];
__device__ __nv_bfloat16 g_kh[BT_*H_*DQK_];
__device__ __nv_bfloat16 g_kl[BT_*H_*DQK_];
// pre-split, pre-transposed V: [b][h][d=64][t=2048]
__device__ __nv_bfloat16 g_vth[B_*H_*DH_*T_];
__device__ __nv_bfloat16 g_vtl[B_*H_*DH_*T_];

// ---------------- TF32 tensor-core GEMM: C[M,N] = A[M,K] @ B[K,N] ----------------
__device__ __forceinline__ unsigned f2tf(float f) {
    unsigned u; asm("cvt.rna.tf32.f32 %0, %1;" : "=r"(u) : "f"(f)); return u;
}

__device__ __forceinline__ void mma_tf32(float* c, const unsigned* a, const unsigned* b) {
    asm volatile(
        "mma.sync.aligned.m16n8k8.row.col.f32.tf32.tf32.f32 "
        "{%0,%1,%2,%3}, {%4,%5,%6,%7}, {%8,%9}, {%0,%1,%2,%3};"
        : "+f"(c[0]), "+f"(c[1]), "+f"(c[2]), "+f"(c[3])
        : "r"(a[0]), "r"(a[1]), "r"(a[2]), "r"(a[3]), "r"(b[0]), "r"(b[1]));
}

__global__ __launch_bounds__(256) void gemm_tf32(
        const float* __restrict__ A, const float* __restrict__ Bm,
        float* __restrict__ C, int M, int N, int K) {
    __shared__ float As[2][128][20];
    __shared__ float Bs[2][16][136];

    const int tid  = threadIdx.x;
    const int lane = tid & 31, warp = tid >> 5;
    const int gr = lane >> 2, tg = lane & 3;
    const int m0 = blockIdx.y << 7;
    const int n0 = blockIdx.x << 7;
    const int wm = (warp >> 2) << 6;
    const int wn = (warp & 3) << 5;

    float acc[4][4][4];
    #pragma unroll
    for (int i = 0; i < 4; i++)
        #pragma unroll
        for (int j = 0; j < 4; j++)
            #pragma unroll
            for (int r = 0; r < 4; r++) acc[i][j][r] = 0.f;

    #define LOAD_STAGE(BUF, K0)                                                       \
    {                                                                                 \
        _Pragma("unroll")                                                             \
        for (int u = 0; u < 2; u++) {                                                 \
            int idx = tid + (u << 8);                                                 \
            int r = idx >> 2, kq = (idx & 3) << 2;                                    \
            unsigned d = (unsigned)__cvta_generic_to_shared(&As[BUF][r][kq]);         \
            const float* s = A + (size_t)(m0 + r) * K + (K0) + kq;                    \
            asm volatile("cp.async.ca.shared.global [%0], [%1], 16;\n"                \
                         :: "r"(d), "l"(s));                                          \
        }                                                                             \
        _Pragma("unroll")                                                             \
        for (int u = 0; u < 2; u++) {                                                 \
            int idx = tid + (u << 8);                                                 \
            int r = idx >> 5, nq = (idx & 31) << 2;                                   \
            unsigned d = (unsigned)__cvta_generic_to_shared(&Bs[BUF][r][nq]);         \
            const float* s = Bm + (size_t)((K0) + r) * N + n0 + nq;                   \
            int sz = (n0 + nq < N) ? 16 : 0;                                          \
            asm volatile("cp.async.ca.shared.global [%0], [%1], 16, %2;\n"            \
                         :: "r"(d), "l"(s), "r"(sz));                                 \
        }                                                                             \
        asm volatile("cp.async.commit_group;\n");                                     \
    }

    int buf = 0;
    LOAD_STAGE(0, 0);

    for (int k0 = 0; k0 < K; k0 += 16) {
        if (k0 + 16 < K) {
            LOAD_STAGE(buf ^ 1, k0 + 16);
            asm volatile("cp.async.wait_group 1;\n");
        } else {
            asm volatile("cp.async.wait_group 0;\n");
        }
        __syncthreads();

        #pragma unroll
        for (int kk = 0; kk < 16; kk += 8) {
            unsigned af[4][4], bf[4][2];
            #pragma unroll
            for (int mt = 0; mt < 4; mt++) {
                int m = wm + (mt << 4);
                af[mt][0] = f2tf(As[buf][m + gr    ][kk + tg    ]);
                af[mt][1] = f2tf(As[buf][m + gr + 8][kk + tg    ]);
                af[mt][2] = f2tf(As[buf][m + gr    ][kk + tg + 4]);
                af[mt][3] = f2tf(As[buf][m + gr + 8][kk + tg + 4]);
            }
            #pragma unroll
            for (int nt = 0; nt < 4; nt++) {
                int n = wn + (nt << 3);
                bf[nt][0] = f2tf(Bs[buf][kk + tg    ][n + gr]);
                bf[nt][1] = f2tf(Bs[buf][kk + tg + 4][n + gr]);
            }
            #pragma unroll
            for (int mt = 0; mt < 4; mt++)
                #pragma unroll
                for (int nt = 0; nt < 4; nt++)
                    mma_tf32(acc[mt][nt], af[mt], bf[nt]);
        }
        __syncthreads();
        buf ^= 1;
    }
    #undef LOAD_STAGE

    #pragma unroll
    for (int mt = 0; mt < 4; mt++) {
        #pragma unroll
        for (int nt = 0; nt < 4; nt++) {
            int m = m0 + wm + (mt << 4) + gr;
            int n = n0 + wn + (nt << 3) + (tg << 1);
            if (n < N) {
                *(float2*)&C[(size_t)m * N + n]       = make_float2(acc[mt][nt][0], acc[mt][nt][1]);
                *(float2*)&C[(size_t)(m + 8) * N + n] = make_float2(acc[mt][nt][2], acc[mt][nt][3]);
            }
        }
    }
}

// ---------------- RoPE + concat + RMS-norm → pre-split bf16 q/k ----------------
__global__ void build_qk_kernel() {
    const int blk = blockIdx.x;           // bt*H + h
    const int bt  = blk >> 4;
    const int h   = blk & 15;
    const int t   = bt & (T_ - 1);
    const int d   = threadIdx.x;          // 0..95

    float qv, kv;
    if (d < DH_) {
        qv = g_qstate[(size_t)bt * DM_ + h * DH_ + d];
        kv = g_kstate[(size_t)bt * DM_ + h * DH_ + d];
    } else {
        const int dr = d - DH_;
        const int j  = dr & 15;
        float inv = powf(10000.f, -(float)j * (1.f / 16.f));
        float ang = (float)t * inv;
        float c = cosf(ang), sn = sinf(ang);
        const float* qr = g_qrot + (size_t)bt * (H_ * DR_) + h * DR_;
        const float* kr = g_krot + (size_t)bt * DR_;
        float x1 = qr[j], x2 = qr[16 + j];
        float y1 = kr[j], y2 = kr[16 + j];
        if (dr < 16) { qv = x1 * c - x2 * sn;  kv = y1 * c - y2 * sn; }
        else         { qv = x1 * sn + x2 * c;  kv = y1 * sn + y2 * c; }
    }
    float q2 = qv * qv, k2 = kv * kv;
    #pragma unroll
    for (int o = 16; o > 0; o >>= 1) {
        q2 += __shfl_xor_sync(0xffffffffu, q2, o);
        k2 += __shfl_xor_sync(0xffffffffu, k2, o);
    }
    __shared__ float pq[3], pk[3];
    const int w = d >> 5;
    if ((d & 31) == 0) { pq[w] = q2; pk[w] = k2; }
    __syncthreads();
    float sq = pq[0] + pq[1] + pq[2];
    float sk = pk[0] + pk[1] + pk[2];
    float rq = rsqrtf(sq * (1.f / 96.f) + 1e-6f);
    float rk = rsqrtf(sk * (1.f / 96.f) + 1e-6f);

    const float scale = 0.10206207261596577f;     // 1/sqrt(96), folded into q
    float qs = qv * rq * scale;
    float ks = kv * rk;
    __nv_bfloat16 qh = __float2bfloat16(qs);
    __nv_bfloat16 kh = __float2bfloat16(ks);
    size_t o = (size_t)blk * DQK_ + d;
    g_qh[o] = qh; g_ql[o] = __float2bfloat16(qs - __bfloat162float(qh));
    g_kh[o] = kh; g_kl[o] = __float2bfloat16(ks - __bfloat162float(kh));
}

// ---------------- V pre-pass: fp32 [bt][h*64+d] -> bf16 hi/lo [b][h][d][t] ----------------
__global__ __launch_bounds__(256) void convert_v() {
    __shared__ float vs[64][65];
    const int tt = blockIdx.x * 64, h = blockIdx.y, b = blockIdx.z;
    const int tid = threadIdx.x;
    for (int i = tid; i < 64 * 16; i += 256) {
        int r = i >> 4, c4 = i & 15;
        float4 v = *(const float4*)(g_vstate + (size_t)(b * T_ + tt + r) * DM_ + h * DH_ + (c4 << 2));
        vs[r][c4 * 4 + 0] = v.x; vs[r][c4 * 4 + 1] = v.y;
        vs[r][c4 * 4 + 2] = v.z; vs[r][c4 * 4 + 3] = v.w;
    }
    __syncthreads();
    for (int i = tid; i < 64 * 64; i += 256) {
        int d = i >> 6, t = i & 63;
        float x = vs[t][d];
        __nv_bfloat16 hb = __float2bfloat16(x);
        size_t o = ((size_t)(b * H_ + h) * DH_ + d) * T_ + tt + t;
        g_vth[o] = hb;
        g_vtl[o] = __float2bfloat16(x - __bfloat162float(hb));
    }
}

// ---------------- flash attention v4: pipelined K/V double-buffer ----------------
__device__ __forceinline__ void mma_bf16(float* c, const unsigned* a, const unsigned* b) {
    asm volatile(
        "mma.sync.aligned.m16n8k16.row.col.f32.bf16.bf16.f32 "
        "{%0,%1,%2,%3}, {%4,%5,%6,%7}, {%8,%9}, {%0,%1,%2,%3};"
        : "+f"(c[0]), "+f"(c[1]), "+f"(c[2]), "+f"(c[3])
        : "r"(a[0]), "r"(a[1]), "r"(a[2]), "r"(a[3]), "r"(b[0]), "r"(b[1]));
}
__device__ __forceinline__ unsigned packbf(float lo, float hi) {
    unsigned r; asm("cvt.rn.bf16x2.f32 %0, %1, %2;" : "=r"(r) : "f"(hi), "f"(lo));
    return r;
}
__device__ __forceinline__ void splitpack(float x0, float x1, unsigned& h, unsigned& l) {
    h = packbf(x0, x1);
    float h0 = __uint_as_float(h << 16);
    float h1 = __uint_as_float(h & 0xffff0000u);
    l = packbf(x0 - h0, x1 - h1);
}
__device__ __forceinline__ void cpa16(void* dst, const void* src) {
    unsigned d = (unsigned)__cvta_generic_to_shared(dst);
    asm volatile("cp.async.ca.shared.global [%0], [%1], 16;\n" :: "r"(d), "l"(src));
}
__device__ __forceinline__ void ldm_x4(unsigned* r, const void* p) {
    unsigned a = (unsigned)__cvta_generic_to_shared(p);
    asm volatile("ldmatrix.sync.aligned.m8n8.x4.shared.b16 {%0,%1,%2,%3}, [%4];"
                 : "=r"(r[0]), "=r"(r[1]), "=r"(r[2]), "=r"(r[3]) : "r"(a));
}

#define QLD 104
#define VLD 72
// per-stage layout (bf16 elems): Kh[64][104] Kl[64][104] Vth[64][72] Vtl[64][72]
#define S_KL   (64*QLD)
#define S_VTH  (2*64*QLD)
#define S_VTL  (2*64*QLD + 64*VLD)
#define STG    (2*64*QLD + 2*64*VLD)     // 22528 elems per stage
#define OFF_Q  (2*STG)                   // Q region after the two stages
#define OFF_QL (OFF_Q + 128*QLD)
#define FL_SMEM ((2*STG + 2*128*QLD) * 2)   // bytes

__global__ __launch_bounds__(256) void flash4() {
    extern __shared__ __nv_bfloat16 sb[];
    __nv_bfloat16* Qh = sb + OFF_Q;
    __nv_bfloat16* Ql = sb + OFF_QL;

    const int qt = gridDim.x - 1 - blockIdx.x;   // heavy tiles first
    const int h  = blockIdx.y;
    const int b  = blockIdx.z;
    const int tid = threadIdx.x, lane = tid & 31, w = tid >> 5;
    const int gr = lane >> 2, tg = lane & 3;
    const int li = lane & 7, lsel = lane >> 3;

    // Q tile (128 rows x 96), hi+lo — group 0
    {
        const __nv_bfloat16* qhg = g_qh + ((size_t)(b * T_ + qt * 128) * H_ + h) * DQK_;
        const __nv_bfloat16* qlg = g_ql + ((size_t)(b * T_ + qt * 128) * H_ + h) * DQK_;
        for (int i = tid; i < 128 * 12; i += 256) {
            int r = i / 12, c = i % 12;
            cpa16(&Qh[r * QLD + c * 8], qhg + (size_t)r * (H_ * DQK_) + c * 8);
            cpa16(&Ql[r * QLD + c * 8], qlg + (size_t)r * (H_ * DQK_) + c * 8);
        }
        asm volatile("cp.async.commit_group;\n");
    }

    const int ktmax = 2 * qt + 1;
    const size_t kvbase = (size_t)(b * H_ + h) * DH_ * T_;

    // prefetch tile kt into stage buffer
    #define PREFETCH(KT, BUF)                                                          \
    {                                                                                  \
        __nv_bfloat16* st = sb + (BUF) * STG;                                          \
        const __nv_bfloat16* khg = g_kh + ((size_t)(b * T_ + (KT) * 64) * H_ + h) * DQK_; \
        const __nv_bfloat16* klg = g_kl + ((size_t)(b * T_ + (KT) * 64) * H_ + h) * DQK_; \
        for (int i = tid; i < 64 * 12; i += 256) {                                     \
            int r = i / 12, c = i % 12;                                                \
            cpa16(&st[r * QLD + c * 8],        khg + (size_t)r * (H_ * DQK_) + c * 8); \
            cpa16(&st[S_KL + r * QLD + c * 8], klg + (size_t)r * (H_ * DQK_) + c * 8); \
        }                                                                              \
        const __nv_bfloat16* vhg = g_vth + kvbase + (KT) * 64;                         \
        const __nv_bfloat16* vlg = g_vtl + kvbase + (KT) * 64;                         \
        for (int i = tid; i < 64 * 8; i += 256) {                                      \
            int d = i >> 3, c = i & 7;                                                 \
            cpa16(&st[S_VTH + d * VLD + c * 8], vhg + (size_t)d * T_ + c * 8);         \
            cpa16(&st[S_VTL + d * VLD + c * 8], vlg + (size_t)d * T_ + c * 8);         \
        }                                                                              \
        asm volatile("cp.async.commit_group;\n");                                     \
    }

    PREFETCH(0, 0);

    float m_[2] = {-1e30f, -1e30f}, l_[2] = {0.f, 0.f};
    float O[8][4];
    #pragma unroll
    for (int nt = 0; nt < 8; nt++)
        #pragma unroll
        for (int j = 0; j < 4; j++) O[nt][j] = 0.f;

    const int rowlo = qt * 128 + w * 16;    // warp's first global row

    for (int kt = 0; kt <= ktmax; kt++) {
        // prefetch next tile into alternate buffer (its prior contents were
        // last read in iter kt-1; the end-of-iter barrier covers the hazard)
        if (kt + 1 <= ktmax) {
            PREFETCH(kt + 1, (kt + 1) & 1);
            asm volatile("cp.async.wait_group 1;\n");
        } else {
            asm volatile("cp.async.wait_group 0;\n");
        }
        __syncthreads();

        const __nv_bfloat16* Kh  = sb + (kt & 1) * STG;
        const __nv_bfloat16* Kl  = Kh + S_KL;
        const __nv_bfloat16* Vth = sb + (kt & 1) * STG + S_VTH;
        const __nv_bfloat16* Vtl = sb + (kt & 1) * STG + S_VTL;

        const bool active = (kt * 64 <= rowlo + 15);
        if (active) {
            // ---- S = Q @ K^T (bf16x3) ----
            float s[8][4];
            #pragma unroll
            for (int nt = 0; nt < 8; nt++)
                #pragma unroll
                for (int j = 0; j < 4; j++) s[nt][j] = 0.f;

            #pragma unroll
            for (int ks = 0; ks < 6; ks++) {
                unsigned ah[4], al[4];
                {
                    int r = w * 16 + ((lsel & 1) << 3) + li;
                    int c = ks * 16 + ((lsel >> 1) << 3);
                    ldm_x4(ah, &Qh[r * QLD + c]);
                    ldm_x4(al, &Ql[r * QLD + c]);
                }
                #pragma unroll
                for (int np = 0; np < 4; np++) {
                    unsigned bh[4], bl[4];
                    int r = np * 16 + ((lsel >> 1) << 3) + li;
                    int c = ks * 16 + ((lsel & 1) << 3);
                    ldm_x4(bh, &Kh[r * QLD + c]);
                    ldm_x4(bl, &Kl[r * QLD + c]);
                    mma_bf16(s[2*np    ], ah, &bh[0]);
                    mma_bf16(s[2*np    ], ah, &bl[0]);
                    mma_bf16(s[2*np    ], al, &bh[0]);
                    mma_bf16(s[2*np + 1], ah, &bh[2]);
                    mma_bf16(s[2*np + 1], ah, &bl[2]);
                    mma_bf16(s[2*np + 1], al, &bh[2]);
                }
            }

            // ---- causal mask (only when tile touches diagonal) ----
            if (kt * 64 + 63 > rowlo) {
                const int rowA = rowlo + gr, rowB = rowA + 8;
                #pragma unroll
                for (int nt = 0; nt < 8; nt++) {
                    int cb = kt * 64 + nt * 8 + 2 * tg;
                    if (cb     > rowA) s[nt][0] = -1e30f;
                    if (cb + 1 > rowA) s[nt][1] = -1e30f;
                    if (cb     > rowB) s[nt][2] = -1e30f;
                    if (cb + 1 > rowB) s[nt][3] = -1e30f;
                }
            }

            // ---- online softmax ----
            float mA = -1e30f, mB = -1e30f;
            #pragma unroll
            for (int nt = 0; nt < 8; nt++) {
                mA = fmaxf(mA, fmaxf(s[nt][0], s[nt][1]));
                mB = fmaxf(mB, fmaxf(s[nt][2], s[nt][3]));
            }
            mA = fmaxf(mA, __shfl_xor_sync(0xffffffffu, mA, 1));
            mA = fmaxf(mA, __shfl_xor_sync(0xffffffffu, mA, 2));
            mB = fmaxf(mB, __shfl_xor_sync(0xffffffffu, mB, 1));
            mB = fmaxf(mB, __shfl_xor_sync(0xffffffffu, mB, 2));
            float nA = fmaxf(m_[0], mA), nB = fmaxf(m_[1], mB);
            float cA = __expf(m_[0] - nA), cB = __expf(m_[1] - nB);
            m_[0] = nA; m_[1] = nB;
            float rA = 0.f, rB = 0.f;
            #pragma unroll
            for (int nt = 0; nt < 8; nt++) {
                s[nt][0] = __expf(s[nt][0] - nA);
                s[nt][1] = __expf(s[nt][1] - nA);
                s[nt][2] = __expf(s[nt][2] - nB);
                s[nt][3] = __expf(s[nt][3] - nB);
                rA += s[nt][0] + s[nt][1];
                rB += s[nt][2] + s[nt][3];
                O[nt][0] *= cA; O[nt][1] *= cA;
                O[nt][2] *= cB; O[nt][3] *= cB;
            }
            rA += __shfl_xor_sync(0xffffffffu, rA, 1);
            rA += __shfl_xor_sync(0xffffffffu, rA, 2);
            rB += __shfl_xor_sync(0xffffffffu, rB, 1);
            rB += __shfl_xor_sync(0xffffffffu, rB, 2);
            l_[0] = l_[0] * cA + rA;
            l_[1] = l_[1] * cB + rB;

            // ---- O += P @ V (bf16x3; P frags straight from S registers) ----
            #pragma unroll
            for (int kk = 0; kk < 4; kk++) {
                unsigned ah[4], al[4];
                splitpack(s[2*kk    ][0], s[2*kk    ][1], ah[0], al[0]);
                splitpack(s[2*kk    ][2], s[2*kk    ][3], ah[1], al[1]);
                splitpack(s[2*kk + 1][0], s[2*kk + 1][1], ah[2], al[2]);
                splitpack(s[2*kk + 1][2], s[2*kk + 1][3], ah[3], al[3]);
                #pragma unroll
                for (int np = 0; np < 4; np++) {
                    unsigned bh[4], bl[4];
                    int r = np * 16 + ((lsel >> 1) << 3) + li;
                    int c = kk * 16 + ((lsel & 1) << 3);
                    ldm_x4(bh, &Vth[r * VLD + c]);
                    ldm_x4(bl, &Vtl[r * VLD + c]);
                    mma_bf16(O[2*np    ], ah, &bh[0]);
                    mma_bf16(O[2*np    ], ah, &bl[0]);
                    mma_bf16(O[2*np    ], al, &bh[0]);
                    mma_bf16(O[2*np + 1], ah, &bh[2]);
                    mma_bf16(O[2*np + 1], ah, &bl[2]);
                    mma_bf16(O[2*np + 1], al, &bh[2]);
                }
            }
        }
        __syncthreads();   // all reads of this stage done before it is overwritten
    }
    #undef PREFETCH

    // epilogue
    float iA = 1.f / l_[0], iB = 1.f / l_[1];
    float* ob = g_attn + (size_t)(b * T_ + qt * 128 + w * 16) * DM_ + h * DH_;
    #pragma unroll
    for (int nt = 0; nt < 8; nt++) {
        int col = nt * 8 + 2 * tg;
        *(float2*)&ob[(size_t)gr * DM_ + col] =
            make_float2(O[nt][0] * iA, O[nt][1] * iA);
        *(float2*)&ob[(size_t)(gr + 8) * DM_ + col] =
            make_float2(O[nt][2] * iB, O[nt][3] * iB);
    }
}

// ---------------- launch ----------------
extern "C" void kernel_launch(void* const* d_in, const int* in_sizes, int n_in,
                              void* d_out, int out_size) {
    const float* x     = (const float*)d_in[0];
    const float* w_dq  = (const float*)d_in[1];
    const float* w_uq  = (const float*)d_in[2];
    const float* w_rq  = (const float*)d_in[3];
    const float* w_dkv = (const float*)d_in[4];
    const float* w_rk  = (const float*)d_in[5];
    const float* w_uk  = (const float*)d_in[6];
    const float* w_uv  = (const float*)d_in[7];
    const float* w_o   = (const float*)d_in[8];
    float* out = (float*)d_out;

    float *cq, *ckv, *krot, *qstate, *qrot, *kstate, *vstate, *attn;
    cudaGetSymbolAddress((void**)&cq,     g_cq);
    cudaGetSymbolAddress((void**)&ckv,    g_ckv);
    cudaGetSymbolAddress((void**)&krot,   g_krot);
    cudaGetSymbolAddress((void**)&qstate, g_qstate);
    cudaGetSymbolAddress((void**)&qrot,   g_qrot);
    cudaGetSymbolAddress((void**)&kstate, g_kstate);
    cudaGetSymbolAddress((void**)&vstate, g_vstate);
    cudaGetSymbolAddress((void**)&attn,   g_attn);

    #define GRID(N) dim3(((N) + 127) / 128, BT_ / 128)
    gemm_tf32<<<GRID(DC1_),     256>>>(x,   w_dq,  cq,     BT_, DC1_,     DM_);
    gemm_tf32<<<GRID(DC_),      256>>>(x,   w_dkv, ckv,    BT_, DC_,      DM_);
    gemm_tf32<<<GRID(DR_),      256>>>(x,   w_rk,  krot,   BT_, DR_,      DM_);
    gemm_tf32<<<GRID(DM_),      256>>>(cq,  w_uq,  qstate, BT_, DM_,      DC1_);
    gemm_tf32<<<GRID(H_ * DR_), 256>>>(cq,  w_rq,  qrot,   BT_, H_ * DR_, DC1_);
    gemm_tf32<<<GRID(DM_),      256>>>(ckv, w_uk,  kstate, BT_, DM_,      DC_);
    gemm_tf32<<<GRID(DM_),      256>>>(ckv, w_uv,  vstate, BT_, DM_,      DC_);

    build_qk_kernel<<<BT_ * H_, 96>>>();
    convert_v<<<dim3(T_ / 64, H_, B_), 256>>>();

    cudaFuncSetAttribute(flash4, cudaFuncAttributeMaxDynamicSharedMemorySize, FL_SMEM);
    flash4<<<dim3(T_ / 128, H_, B_), 256, FL_SMEM>>>();

    gemm_tf32<<<GRID(DM_), 256>>>(attn, w_o, out, BT_, DM_, DM_);
    #undef GRID
}

// round 7
// speedup vs baseline: 3.2853x; 1.0665x over previous
#include <cuda_runtime.h>
#include <cuda_bf16.h>
#include <stdint.h>
#include <math.h>

#define B_   2
#define T_   2048
#define BT_  (B_*T_)
#define DM_  1024
#define H_   16
#define DH_  64
#define DC1_ 384
#define DC_  256
#define DR_  32
#define DQK_ 96

// ---------------- scratch (device globals: alloc-free) ----------------
// packed weights
__device__ float g_w1[DM_*672];      // [1024][384+256+32]  = [w_dq|w_dkv|w_rk]
__device__ float g_w2[DC1_*1536];    // [384][1024+512]     = [w_uq|w_rq]
__device__ float g_w3[DC_*2048];     // [256][1024+1024]    = [w_uk|w_uv]
// fused activations
__device__ float g_c1[BT_*672];      // [cq | ckv | krot]
__device__ float g_c2[BT_*1536];     // [qstate | qrot]
__device__ float g_c3[BT_*2048];     // [kstate | vstate]
__device__ float g_attn[BT_*DM_];
// pre-split bf16 hi/lo q_final (scale folded) and k_final: [bt][h][96]
__device__ __nv_bfloat16 g_qh[BT_*H_*DQK_];
__device__ __nv_bfloat16 g_ql[BT_*H_*DQK_];
__device__ __nv_bfloat16 g_kh[BT_*H_*DQK_];
__device__ __nv_bfloat16 g_kl[BT_*H_*DQK_];
// pre-split, pre-transposed V: [b][h][d=64][t=2048]
__device__ __nv_bfloat16 g_vth[B_*H_*DH_*T_];
__device__ __nv_bfloat16 g_vtl[B_*H_*DH_*T_];

// ---------------- weight packing (exact copies) ----------------
__global__ void pack_w1(const float* __restrict__ wdq, const float* __restrict__ wdkv,
                        const float* __restrict__ wrk) {
    for (int i = blockIdx.x * 256 + threadIdx.x; i < DM_ * 672; i += gridDim.x * 256) {
        int k = i / 672, n = i % 672;
        float v;
        if (n < 384)      v = wdq [k * 384 + n];
        else if (n < 640) v = wdkv[k * 256 + (n - 384)];
        else              v = wrk [k * 32  + (n - 640)];
        g_w1[i] = v;
    }
}
__global__ void pack_w2(const float* __restrict__ wuq, const float* __restrict__ wrq) {
    for (int i = blockIdx.x * 256 + threadIdx.x; i < DC1_ * 1536; i += gridDim.x * 256) {
        int k = i / 1536, n = i % 1536;
        g_w2[i] = (n < 1024) ? wuq[k * 1024 + n] : wrq[k * 512 + (n - 1024)];
    }
}
__global__ void pack_w3(const float* __restrict__ wuk, const float* __restrict__ wuv) {
    for (int i = blockIdx.x * 256 + threadIdx.x; i < DC_ * 2048; i += gridDim.x * 256) {
        int k = i / 2048, n = i % 2048;
        g_w3[i] = (n < 1024) ? wuk[k * 1024 + n] : wuv[k * 1024 + (n - 1024)];
    }
}

// ---------------- TF32 tensor-core GEMM: C[M,N] = A[M,K(lda)] @ B[K,N] ----------------
__device__ __forceinline__ unsigned f2tf(float f) {
    unsigned u; asm("cvt.rna.tf32.f32 %0, %1;" : "=r"(u) : "f"(f)); return u;
}
__device__ __forceinline__ void mma_tf32(float* c, const unsigned* a, const unsigned* b) {
    asm volatile(
        "mma.sync.aligned.m16n8k8.row.col.f32.tf32.tf32.f32 "
        "{%0,%1,%2,%3}, {%4,%5,%6,%7}, {%8,%9}, {%0,%1,%2,%3};"
        : "+f"(c[0]), "+f"(c[1]), "+f"(c[2]), "+f"(c[3])
        : "r"(a[0]), "r"(a[1]), "r"(a[2]), "r"(a[3]), "r"(b[0]), "r"(b[1]));
}

__global__ __launch_bounds__(256) void gemm_tf32(
        const float* __restrict__ A, const float* __restrict__ Bm,
        float* __restrict__ C, int M, int N, int K, int lda, int ldc) {
    __shared__ float As[2][128][20];
    __shared__ float Bs[2][16][136];

    const int tid  = threadIdx.x;
    const int lane = tid & 31, warp = tid >> 5;
    const int gr = lane >> 2, tg = lane & 3;
    const int m0 = blockIdx.y << 7;
    const int n0 = blockIdx.x << 7;
    const int wm = (warp >> 2) << 6;
    const int wn = (warp & 3) << 5;

    float acc[4][4][4];
    #pragma unroll
    for (int i = 0; i < 4; i++)
        #pragma unroll
        for (int j = 0; j < 4; j++)
            #pragma unroll
            for (int r = 0; r < 4; r++) acc[i][j][r] = 0.f;

    #define LOAD_STAGE(BUF, K0)                                                       \
    {                                                                                 \
        _Pragma("unroll")                                                             \
        for (int u = 0; u < 2; u++) {                                                 \
            int idx = tid + (u << 8);                                                 \
            int r = idx >> 2, kq = (idx & 3) << 2;                                    \
            unsigned d = (unsigned)__cvta_generic_to_shared(&As[BUF][r][kq]);         \
            const float* s = A + (size_t)(m0 + r) * lda + (K0) + kq;                  \
            asm volatile("cp.async.ca.shared.global [%0], [%1], 16;\n"                \
                         :: "r"(d), "l"(s));                                          \
        }                                                                             \
        _Pragma("unroll")                                                             \
        for (int u = 0; u < 2; u++) {                                                 \
            int idx = tid + (u << 8);                                                 \
            int r = idx >> 5, nq = (idx & 31) << 2;                                   \
            unsigned d = (unsigned)__cvta_generic_to_shared(&Bs[BUF][r][nq]);         \
            const float* s = Bm + (size_t)((K0) + r) * N + n0 + nq;                   \
            int sz = (n0 + nq < N) ? 16 : 0;                                          \
            asm volatile("cp.async.ca.shared.global [%0], [%1], 16, %2;\n"            \
                         :: "r"(d), "l"(s), "r"(sz));                                 \
        }                                                                             \
        asm volatile("cp.async.commit_group;\n");                                     \
    }

    int buf = 0;
    LOAD_STAGE(0, 0);

    for (int k0 = 0; k0 < K; k0 += 16) {
        if (k0 + 16 < K) {
            LOAD_STAGE(buf ^ 1, k0 + 16);
            asm volatile("cp.async.wait_group 1;\n");
        } else {
            asm volatile("cp.async.wait_group 0;\n");
        }
        __syncthreads();

        #pragma unroll
        for (int kk = 0; kk < 16; kk += 8) {
            unsigned af[4][4], bf[4][2];
            #pragma unroll
            for (int mt = 0; mt < 4; mt++) {
                int m = wm + (mt << 4);
                af[mt][0] = f2tf(As[buf][m + gr    ][kk + tg    ]);
                af[mt][1] = f2tf(As[buf][m + gr + 8][kk + tg    ]);
                af[mt][2] = f2tf(As[buf][m + gr    ][kk + tg + 4]);
                af[mt][3] = f2tf(As[buf][m + gr + 8][kk + tg + 4]);
            }
            #pragma unroll
            for (int nt = 0; nt < 4; nt++) {
                int n = wn + (nt << 3);
                bf[nt][0] = f2tf(Bs[buf][kk + tg    ][n + gr]);
                bf[nt][1] = f2tf(Bs[buf][kk + tg + 4][n + gr]);
            }
            #pragma unroll
            for (int mt = 0; mt < 4; mt++)
                #pragma unroll
                for (int nt = 0; nt < 4; nt++)
                    mma_tf32(acc[mt][nt], af[mt], bf[nt]);
        }
        __syncthreads();
        buf ^= 1;
    }
    #undef LOAD_STAGE

    #pragma unroll
    for (int mt = 0; mt < 4; mt++) {
        #pragma unroll
        for (int nt = 0; nt < 4; nt++) {
            int m = m0 + wm + (mt << 4) + gr;
            int n = n0 + wn + (nt << 3) + (tg << 1);
            if (n < N) {
                *(float2*)&C[(size_t)m * ldc + n]       = make_float2(acc[mt][nt][0], acc[mt][nt][1]);
                *(float2*)&C[(size_t)(m + 8) * ldc + n] = make_float2(acc[mt][nt][2], acc[mt][nt][3]);
            }
        }
    }
}

// ---------------- RoPE + concat + RMS-norm → pre-split bf16 q/k ----------------
__global__ void build_qk_kernel() {
    const int blk = blockIdx.x;           // bt*H + h
    const int bt  = blk >> 4;
    const int h   = blk & 15;
    const int t   = bt & (T_ - 1);
    const int d   = threadIdx.x;          // 0..95

    float qv, kv;
    if (d < DH_) {
        qv = g_c2[(size_t)bt * 1536 + h * DH_ + d];
        kv = g_c3[(size_t)bt * 2048 + h * DH_ + d];
    } else {
        const int dr = d - DH_;
        const int j  = dr & 15;
        float inv = powf(10000.f, -(float)j * (1.f / 16.f));
        float ang = (float)t * inv;
        float c = cosf(ang), sn = sinf(ang);
        const float* qr = g_c2 + (size_t)bt * 1536 + 1024 + h * DR_;
        const float* kr = g_c1 + (size_t)bt * 672 + 640;
        float x1 = qr[j], x2 = qr[16 + j];
        float y1 = kr[j], y2 = kr[16 + j];
        if (dr < 16) { qv = x1 * c - x2 * sn;  kv = y1 * c - y2 * sn; }
        else         { qv = x1 * sn + x2 * c;  kv = y1 * sn + y2 * c; }
    }
    float q2 = qv * qv, k2 = kv * kv;
    #pragma unroll
    for (int o = 16; o > 0; o >>= 1) {
        q2 += __shfl_xor_sync(0xffffffffu, q2, o);
        k2 += __shfl_xor_sync(0xffffffffu, k2, o);
    }
    __shared__ float pq[3], pk[3];
    const int w = d >> 5;
    if ((d & 31) == 0) { pq[w] = q2; pk[w] = k2; }
    __syncthreads();
    float sq = pq[0] + pq[1] + pq[2];
    float sk = pk[0] + pk[1] + pk[2];
    float rq = rsqrtf(sq * (1.f / 96.f) + 1e-6f);
    float rk = rsqrtf(sk * (1.f / 96.f) + 1e-6f);

    const float scale = 0.10206207261596577f;     // 1/sqrt(96), folded into q
    float qs = qv * rq * scale;
    float ks = kv * rk;
    __nv_bfloat16 qh = __float2bfloat16(qs);
    __nv_bfloat16 kh = __float2bfloat16(ks);
    size_t o = (size_t)blk * DQK_ + d;
    g_qh[o] = qh; g_ql[o] = __float2bfloat16(qs - __bfloat162float(qh));
    g_kh[o] = kh; g_kl[o] = __float2bfloat16(ks - __bfloat162float(kh));
}

// ---------------- V pre-pass: fp32 [bt][1024 + h*64 + d] -> bf16 hi/lo [b][h][d][t] ----------------
__global__ __launch_bounds__(256) void convert_v() {
    __shared__ float vs[64][65];
    const int tt = blockIdx.x * 64, h = blockIdx.y, b = blockIdx.z;
    const int tid = threadIdx.x;
    for (int i = tid; i < 64 * 16; i += 256) {
        int r = i >> 4, c4 = i & 15;
        float4 v = *(const float4*)(g_c3 + (size_t)(b * T_ + tt + r) * 2048 + 1024 + h * DH_ + (c4 << 2));
        vs[r][c4 * 4 + 0] = v.x; vs[r][c4 * 4 + 1] = v.y;
        vs[r][c4 * 4 + 2] = v.z; vs[r][c4 * 4 + 3] = v.w;
    }
    __syncthreads();
    for (int i = tid; i < 64 * 64; i += 256) {
        int d = i >> 6, t = i & 63;
        float x = vs[t][d];
        __nv_bfloat16 hb = __float2bfloat16(x);
        size_t o = ((size_t)(b * H_ + h) * DH_ + d) * T_ + tt + t;
        g_vth[o] = hb;
        g_vtl[o] = __float2bfloat16(x - __bfloat162float(hb));
    }
}

// ---------------- flash attention v5: Q in registers, 3-stage K/V ring ----------------
__device__ __forceinline__ void mma_bf16(float* c, const unsigned* a, const unsigned* b) {
    asm volatile(
        "mma.sync.aligned.m16n8k16.row.col.f32.bf16.bf16.f32 "
        "{%0,%1,%2,%3}, {%4,%5,%6,%7}, {%8,%9}, {%0,%1,%2,%3};"
        : "+f"(c[0]), "+f"(c[1]), "+f"(c[2]), "+f"(c[3])
        : "r"(a[0]), "r"(a[1]), "r"(a[2]), "r"(a[3]), "r"(b[0]), "r"(b[1]));
}
__device__ __forceinline__ unsigned packbf(float lo, float hi) {
    unsigned r; asm("cvt.rn.bf16x2.f32 %0, %1, %2;" : "=r"(r) : "f"(hi), "f"(lo));
    return r;
}
__device__ __forceinline__ void splitpack(float x0, float x1, unsigned& h, unsigned& l) {
    h = packbf(x0, x1);
    float h0 = __uint_as_float(h << 16);
    float h1 = __uint_as_float(h & 0xffff0000u);
    l = packbf(x0 - h0, x1 - h1);
}
__device__ __forceinline__ void cpa16(void* dst, const void* src) {
    unsigned d = (unsigned)__cvta_generic_to_shared(dst);
    asm volatile("cp.async.ca.shared.global [%0], [%1], 16;\n" :: "r"(d), "l"(src));
}
__device__ __forceinline__ void ldm_x4(unsigned* r, const void* p) {
    unsigned a = (unsigned)__cvta_generic_to_shared(p);
    asm volatile("ldmatrix.sync.aligned.m8n8.x4.shared.b16 {%0,%1,%2,%3}, [%4];"
                 : "=r"(r[0]), "=r"(r[1]), "=r"(r[2]), "=r"(r[3]) : "r"(a));
}

#define QLD 104
#define VLD 72
// per-stage layout (bf16 elems): Kh[64][104] Kl[64][104] Vth[64][72] Vtl[64][72]
#define S_KL   (64*QLD)
#define S_VTH  (2*64*QLD)
#define S_VTL  (2*64*QLD + 64*VLD)
#define STG    (2*64*QLD + 2*64*VLD)     // 22528 elems per stage
#define FL_SMEM (3*STG*2)                // 3-stage ring, bytes

__global__ __launch_bounds__(256) void flash5() {
    extern __shared__ __nv_bfloat16 sb[];

    const int qt = gridDim.x - 1 - blockIdx.x;   // heavy tiles first
    const int h  = blockIdx.y;
    const int b  = blockIdx.z;
    const int tid = threadIdx.x, lane = tid & 31, w = tid >> 5;
    const int gr = lane >> 2, tg = lane & 3;
    const int li = lane & 7, lsel = lane >> 3;

    const int ktmax = 2 * qt + 1;
    const size_t kvbase = (size_t)(b * H_ + h) * DH_ * T_;

    #define PREFETCH(KT, BUF)                                                          \
    {                                                                                  \
        __nv_bfloat16* st = sb + (BUF) * STG;                                          \
        const __nv_bfloat16* khg = g_kh + ((size_t)(b * T_ + (KT) * 64) * H_ + h) * DQK_; \
        const __nv_bfloat16* klg = g_kl + ((size_t)(b * T_ + (KT) * 64) * H_ + h) * DQK_; \
        for (int i = tid; i < 64 * 12; i += 256) {                                     \
            int r = i / 12, c = i % 12;                                                \
            cpa16(&st[r * QLD + c * 8],        khg + (size_t)r * (H_ * DQK_) + c * 8); \
            cpa16(&st[S_KL + r * QLD + c * 8], klg + (size_t)r * (H_ * DQK_) + c * 8); \
        }                                                                              \
        const __nv_bfloat16* vhg = g_vth + kvbase + (KT) * 64;                         \
        const __nv_bfloat16* vlg = g_vtl + kvbase + (KT) * 64;                         \
        for (int i = tid; i < 64 * 8; i += 256) {                                      \
            int d = i >> 3, c = i & 7;                                                 \
            cpa16(&st[S_VTH + d * VLD + c * 8], vhg + (size_t)d * T_ + c * 8);         \
            cpa16(&st[S_VTL + d * VLD + c * 8], vlg + (size_t)d * T_ + c * 8);         \
        }                                                                              \
        asm volatile("cp.async.commit_group;\n");                                     \
    }

    PREFETCH(0, 0);
    if (1 <= ktmax) PREFETCH(1, 1);

    // ---- Q fragments -> registers (m16n8k16 A-frag layout, direct gmem loads) ----
    unsigned qah[6][4], qal[6][4];
    {
        const int r0 = qt * 128 + w * 16 + gr;
        const __nv_bfloat16* qhg = g_qh + ((size_t)(b * T_ + r0) * H_ + h) * DQK_;
        const __nv_bfloat16* qlg = g_ql + ((size_t)(b * T_ + r0) * H_ + h) * DQK_;
        const size_t rs = (size_t)8 * H_ * DQK_;   // +8 rows
        #pragma unroll
        for (int ks = 0; ks < 6; ks++) {
            int c = ks * 16 + 2 * tg;
            qah[ks][0] = *(const unsigned*)(qhg + c);
            qah[ks][1] = *(const unsigned*)(qhg + rs + c);
            qah[ks][2] = *(const unsigned*)(qhg + c + 8);
            qah[ks][3] = *(const unsigned*)(qhg + rs + c + 8);
            qal[ks][0] = *(const unsigned*)(qlg + c);
            qal[ks][1] = *(const unsigned*)(qlg + rs + c);
            qal[ks][2] = *(const unsigned*)(qlg + c + 8);
            qal[ks][3] = *(const unsigned*)(qlg + rs + c + 8);
        }
    }

    float m_[2] = {-1e30f, -1e30f}, l_[2] = {0.f, 0.f};
    float O[8][4];
    #pragma unroll
    for (int nt = 0; nt < 8; nt++)
        #pragma unroll
        for (int j = 0; j < 4; j++) O[nt][j] = 0.f;

    const int rowlo = qt * 128 + w * 16;

    for (int kt = 0; kt <= ktmax; kt++) {
        if (kt < ktmax) asm volatile("cp.async.wait_group 1;\n");
        else            asm volatile("cp.async.wait_group 0;\n");
        __syncthreads();   // stage kt visible to all; stage (kt+2)%3 reads (iter kt-1) done

        if (kt + 2 <= ktmax) PREFETCH(kt + 2, (kt + 2) % 3);

        const __nv_bfloat16* st  = sb + (kt % 3) * STG;
        const __nv_bfloat16* Kh  = st;
        const __nv_bfloat16* Kl  = st + S_KL;
        const __nv_bfloat16* Vth = st + S_VTH;
        const __nv_bfloat16* Vtl = st + S_VTL;

        const bool active = (kt * 64 <= rowlo + 15);
        if (active) {
            // ---- S = Q @ K^T (bf16x3) ----
            float s[8][4];
            #pragma unroll
            for (int nt = 0; nt < 8; nt++)
                #pragma unroll
                for (int j = 0; j < 4; j++) s[nt][j] = 0.f;

            #pragma unroll
            for (int ks = 0; ks < 6; ks++) {
                #pragma unroll
                for (int np = 0; np < 4; np++) {
                    unsigned bh[4], bl[4];
                    int r = np * 16 + ((lsel >> 1) << 3) + li;
                    int c = ks * 16 + ((lsel & 1) << 3);
                    ldm_x4(bh, &Kh[r * QLD + c]);
                    ldm_x4(bl, &Kl[r * QLD + c]);
                    mma_bf16(s[2*np    ], qah[ks], &bh[0]);
                    mma_bf16(s[2*np    ], qah[ks], &bl[0]);
                    mma_bf16(s[2*np    ], qal[ks], &bh[0]);
                    mma_bf16(s[2*np + 1], qah[ks], &bh[2]);
                    mma_bf16(s[2*np + 1], qah[ks], &bl[2]);
                    mma_bf16(s[2*np + 1], qal[ks], &bh[2]);
                }
            }

            // ---- causal mask ----
            if (kt * 64 + 63 > rowlo) {
                const int rowA = rowlo + gr, rowB = rowA + 8;
                #pragma unroll
                for (int nt = 0; nt < 8; nt++) {
                    int cb = kt * 64 + nt * 8 + 2 * tg;
                    if (cb     > rowA) s[nt][0] = -1e30f;
                    if (cb + 1 > rowA) s[nt][1] = -1e30f;
                    if (cb     > rowB) s[nt][2] = -1e30f;
                    if (cb + 1 > rowB) s[nt][3] = -1e30f;
                }
            }

            // ---- online softmax ----
            float mA = -1e30f, mB = -1e30f;
            #pragma unroll
            for (int nt = 0; nt < 8; nt++) {
                mA = fmaxf(mA, fmaxf(s[nt][0], s[nt][1]));
                mB = fmaxf(mB, fmaxf(s[nt][2], s[nt][3]));
            }
            mA = fmaxf(mA, __shfl_xor_sync(0xffffffffu, mA, 1));
            mA = fmaxf(mA, __shfl_xor_sync(0xffffffffu, mA, 2));
            mB = fmaxf(mB, __shfl_xor_sync(0xffffffffu, mB, 1));
            mB = fmaxf(mB, __shfl_xor_sync(0xffffffffu, mB, 2));
            float nA = fmaxf(m_[0], mA), nB = fmaxf(m_[1], mB);
            float cA = __expf(m_[0] - nA), cB = __expf(m_[1] - nB);
            m_[0] = nA; m_[1] = nB;
            float rA = 0.f, rB = 0.f;
            #pragma unroll
            for (int nt = 0; nt < 8; nt++) {
                s[nt][0] = __expf(s[nt][0] - nA);
                s[nt][1] = __expf(s[nt][1] - nA);
                s[nt][2] = __expf(s[nt][2] - nB);
                s[nt][3] = __expf(s[nt][3] - nB);
                rA += s[nt][0] + s[nt][1];
                rB += s[nt][2] + s[nt][3];
                O[nt][0] *= cA; O[nt][1] *= cA;
                O[nt][2] *= cB; O[nt][3] *= cB;
            }
            rA += __shfl_xor_sync(0xffffffffu, rA, 1);
            rA += __shfl_xor_sync(0xffffffffu, rA, 2);
            rB += __shfl_xor_sync(0xffffffffu, rB, 1);
            rB += __shfl_xor_sync(0xffffffffu, rB, 2);
            l_[0] = l_[0] * cA + rA;
            l_[1] = l_[1] * cB + rB;

            // ---- O += P @ V (bf16x3; P frags straight from S registers) ----
            #pragma unroll
            for (int kk = 0; kk < 4; kk++) {
                unsigned ah[4], al[4];
                splitpack(s[2*kk    ][0], s[2*kk    ][1], ah[0], al[0]);
                splitpack(s[2*kk    ][2], s[2*kk    ][3], ah[1], al[1]);
                splitpack(s[2*kk + 1][0], s[2*kk + 1][1], ah[2], al[2]);
                splitpack(s[2*kk + 1][2], s[2*kk + 1][3], ah[3], al[3]);
                #pragma unroll
                for (int np = 0; np < 4; np++) {
                    unsigned bh[4], bl[4];
                    int r = np * 16 + ((lsel >> 1) << 3) + li;
                    int c = kk * 16 + ((lsel & 1) << 3);
                    ldm_x4(bh, &Vth[r * VLD + c]);
                    ldm_x4(bl, &Vtl[r * VLD + c]);
                    mma_bf16(O[2*np    ], ah, &bh[0]);
                    mma_bf16(O[2*np    ], ah, &bl[0]);
                    mma_bf16(O[2*np    ], al, &bh[0]);
                    mma_bf16(O[2*np + 1], ah, &bh[2]);
                    mma_bf16(O[2*np + 1], ah, &bl[2]);
                    mma_bf16(O[2*np + 1], al, &bh[2]);
                }
            }
        }
    }
    #undef PREFETCH

    // epilogue
    float iA = 1.f / l_[0], iB = 1.f / l_[1];
    float* ob = g_attn + (size_t)(b * T_ + qt * 128 + w * 16) * DM_ + h * DH_;
    #pragma unroll
    for (int nt = 0; nt < 8; nt++) {
        int col = nt * 8 + 2 * tg;
        *(float2*)&ob[(size_t)gr * DM_ + col] =
            make_float2(O[nt][0] * iA, O[nt][1] * iA);
        *(float2*)&ob[(size_t)(gr + 8) * DM_ + col] =
            make_float2(O[nt][2] * iB, O[nt][3] * iB);
    }
}

// ---------------- launch ----------------
extern "C" void kernel_launch(void* const* d_in, const int* in_sizes, int n_in,
                              void* d_out, int out_size) {
    const float* x     = (const float*)d_in[0];
    const float* w_dq  = (const float*)d_in[1];
    const float* w_uq  = (const float*)d_in[2];
    const float* w_rq  = (const float*)d_in[3];
    const float* w_dkv = (const float*)d_in[4];
    const float* w_rk  = (const float*)d_in[5];
    const float* w_uk  = (const float*)d_in[6];
    const float* w_uv  = (const float*)d_in[7];
    const float* w_o   = (const float*)d_in[8];
    float* out = (float*)d_out;

    float *w1, *w2, *w3, *c1, *c2, *c3, *attn;
    cudaGetSymbolAddress((void**)&w1,   g_w1);
    cudaGetSymbolAddress((void**)&w2,   g_w2);
    cudaGetSymbolAddress((void**)&w3,   g_w3);
    cudaGetSymbolAddress((void**)&c1,   g_c1);
    cudaGetSymbolAddress((void**)&c2,   g_c2);
    cudaGetSymbolAddress((void**)&c3,   g_c3);
    cudaGetSymbolAddress((void**)&attn, g_attn);

    pack_w1<<<256, 256>>>(w_dq, w_dkv, w_rk);
    pack_w2<<<256, 256>>>(w_uq, w_rq);
    pack_w3<<<256, 256>>>(w_uk, w_uv);

    #define GRID(N) dim3(((N) + 127) / 128, BT_ / 128)
    gemm_tf32<<<GRID(672),  256>>>(x,        w1,  c1,  BT_, 672,  DM_,  DM_,  672);
    gemm_tf32<<<GRID(1536), 256>>>(c1,       w2,  c2,  BT_, 1536, DC1_, 672,  1536);
    gemm_tf32<<<GRID(2048), 256>>>(c1 + 384, w3,  c3,  BT_, 2048, DC_,  672,  2048);

    build_qk_kernel<<<BT_ * H_, 96>>>();
    convert_v<<<dim3(T_ / 64, H_, B_), 256>>>();

    cudaFuncSetAttribute(flash5, cudaFuncAttributeMaxDynamicSharedMemorySize, FL_SMEM);
    flash5<<<dim3(T_ / 128, H_, B_), 256, FL_SMEM>>>();

    gemm_tf32<<<GRID(DM_), 256>>>(attn, w_o, out, BT_, DM_, DM_, DM_, DM_);
    #undef GRID
}